// round 4
// baseline (speedup 1.0000x reference)
#include <cuda_runtime.h>
#include <cuda_fp16.h>
#include <math.h>

#define NN 10000
#define EE 160000
#define CC 64
#define RMAXF 5.0f

// ---------------- device scratch ----------------
__device__ __half d_zh[2][EE * 16];
__device__ float d_sh12[EE * 12];
__device__ unsigned char d_act[EE];
__device__ int   d_count[NN];          // zero-init; self-restored by k_scan1
__device__ int   d_offs[NN + 1];
__device__ int   d_cursor[NN];
__device__ int2  d_sedge[EE];
__device__ int   d_bsum[16];
__device__ float d_hup[NN * CC];
__device__ __half d_hh[NN * CC];
__device__ __half d_aggh[NN * 576];
__device__ __half d_W2T[2][576 * 16];  // [cg][m]
__device__ __half d_BT[2][64 * 640];   // [n][k]
__device__ __half d_WupT[64 * 64];     // W_up[1] transposed [o][i]

__device__ __forceinline__ void mma16816(float& c0, float& c1, float& c2, float& c3,
                                         unsigned a0, unsigned a1, unsigned a2, unsigned a3,
                                         unsigned b0, unsigned b1) {
    asm volatile(
        "mma.sync.aligned.m16n8k16.row.col.f32.f16.f16.f32 "
        "{%0,%1,%2,%3},{%4,%5,%6,%7},{%8,%9},{%0,%1,%2,%3};\n"
        : "+f"(c0), "+f"(c1), "+f"(c2), "+f"(c3)
        : "r"(a0), "r"(a1), "r"(a2), "r"(a3), "r"(b0), "r"(b1));
}

// ---------------- weight prep (fp32 -> fp16, transposed) ----------------
__global__ void k_prep(const float* __restrict__ Wr2, const float* __restrict__ Wmix,
                       const float* __restrict__ Wself, const float* __restrict__ Wup) {
    int i = blockIdx.x * 256 + threadIdx.x;
    if (i < 2 * 9216) {
        int t = i / 9216, r = i - t * 9216, cg = r >> 4, m = r & 15;
        d_W2T[t][r] = __float2half(Wr2[t * 9216 + m * 576 + cg]);
    }
    int j = i - 18432;
    if (j >= 0 && j < 2 * 40960) {
        int t = j / 40960, r = j - t * 40960, n = r / 640, k = r - n * 640;
        float v = (k < 576) ? Wmix[t * 36864 + k * 64 + n] : Wself[t * 4096 + (k - 576) * 64 + n];
        d_BT[t][r] = __float2half(v);
    }
    int q = i - 18432 - 81920;
    if (q >= 0 && q < 4096) {
        int o = q >> 6, ii = q & 63;
        d_WupT[q] = __float2half(Wup[4096 + ii * 64 + o]);
    }
}

// ---------------- embed: h0, h0_half, hup0, out row0 ----------------
__global__ __launch_bounds__(64) void k_embed(const float* __restrict__ na,
                        const float* __restrict__ We, const float* __restrict__ ae,
                        const float* __restrict__ Wup, float* __restrict__ out) {
    __shared__ float hs[64];
    int n = blockIdx.x, c = threadIdx.x;
    float acc = 0.f;
#pragma unroll
    for (int k = 0; k < 10; k++) acc = fmaf(na[n * 10 + k], We[k * 64 + c], acc);
    hs[c] = acc;
    d_hh[n * 64 + c] = __float2half(acc);
    if (c == 0) {
        float r = 0.f;
#pragma unroll
        for (int k = 0; k < 10; k++) r = fmaf(na[n * 10 + k], ae[k], r);
        out[n] = r;
    }
    __syncthreads();
    float hu = 0.f;
#pragma unroll
    for (int k = 0; k < 64; k++) hu = fmaf(hs[k], Wup[k * 64 + c], hu);
    d_hup[n * 64 + c] = hu;
}

// ---------------- per-edge geometry ----------------
__global__ __launch_bounds__(256) void k_geom(const float* __restrict__ pos,
                       const float* __restrict__ shifts,
                       const int* __restrict__ ei, const float* __restrict__ Wr1) {
    __shared__ float Ws[256];
    Ws[threadIdx.x] = Wr1[threadIdx.x];
    __syncthreads();
    int e = blockIdx.x * blockDim.x + threadIdx.x;
    if (e >= EE) return;
    int s  = ei[e];
    int rv = ei[EE + e];
    float vx = pos[rv * 3 + 0] - pos[s * 3 + 0] + shifts[e * 3 + 0];
    float vy = pos[rv * 3 + 1] - pos[s * 3 + 1] + shifts[e * 3 + 1];
    float vz = pos[rv * 3 + 2] - pos[s * 3 + 2] + shifts[e * 3 + 2];
    float r = sqrtf(vx * vx + vy * vy + vz * vz) + 1e-9f;
    float xx = r * (1.0f / RMAXF);
    bool act = (xx < 1.0f);
    d_act[e] = act ? 1 : 0;
    if (!act) return;
    atomicAdd(&d_count[rv], 1);

    float inv = __fdividef(1.0f, r);
    float ux = vx * inv, uy = vy * inv, uz = vz * inv;
    const float s3 = 1.7320508075688772f, s5 = 2.2360679774997896f, s15 = 3.872983346207417f;
    float4 fA = make_float4(1.0f, s3 * ux, s3 * uy, s3 * uz);
    float4 fB = make_float4(s15 * ux * uy, s15 * uy * uz,
                            0.5f * s5 * (3.0f * uz * uz - 1.0f), s15 * ux * uz);
    float4 fC = make_float4(0.5f * s15 * (ux * ux - uy * uy), 0.f, 0.f, 0.f);
    float4* shp = (float4*)&d_sh12[(long)e * 12];
    shp[0] = fA; shp[1] = fB; shp[2] = fC;

    float th = 3.14159265358979323846f * xx;
    float s1, c1;
    __sincosf(th, &s1, &c1);
    float x2 = xx * xx;
    float x6 = x2 * x2 * x2;
    float fc = 1.0f + x6 * (-28.0f + xx * (48.0f - 21.0f * xx));
    float pref = 0.6324555320336759f * inv * fc;
    float ef[8];
    float sp = 0.0f, sc = s1, c2 = 2.0f * c1;
#pragma unroll
    for (int n = 0; n < 8; n++) {
        ef[n] = pref * sc;
        float nx = c2 * sc - sp;
        sp = sc; sc = nx;
    }
#pragma unroll
    for (int t = 0; t < 2; t++) {
        float a[16];
#pragma unroll
        for (int m = 0; m < 16; m++) {
            float acc = 0.f;
#pragma unroll
            for (int n = 0; n < 8; n++) acc = fmaf(ef[n], Ws[t * 128 + n * 16 + m], acc);
            a[m] = __fdividef(acc, 1.0f + __expf(-acc));
        }
        __half2 hz[8];
#pragma unroll
        for (int q = 0; q < 8; q++) hz[q] = __floats2half2_rn(a[2 * q], a[2 * q + 1]);
        uint4* zp = (uint4*)&d_zh[t][(long)e * 16];
        zp[0] = *(uint4*)&hz[0];
        zp[1] = *(uint4*)&hz[4];
    }
}

// ---------------- scan (2 kernels) + scatter ----------------
__global__ __launch_bounds__(1024) void k_scan1() {
    __shared__ int ws[32];
    int t = threadIdx.x, lane = t & 31, w = t >> 5;
    int idx = blockIdx.x * 1024 + t;
    int v = 0;
    if (idx < NN) { v = d_count[idx]; d_count[idx] = 0; }   // self-restore for next replay
    int inc = v;
#pragma unroll
    for (int o = 1; o < 32; o <<= 1) {
        int u = __shfl_up_sync(0xffffffffu, inc, o);
        if (lane >= o) inc += u;
    }
    if (lane == 31) ws[w] = inc;
    __syncthreads();
    if (w == 0) {
        int x = ws[lane];
        int xi = x;
#pragma unroll
        for (int o = 1; o < 32; o <<= 1) {
            int u = __shfl_up_sync(0xffffffffu, xi, o);
            if (lane >= o) xi += u;
        }
        ws[lane] = xi - x;
    }
    __syncthreads();
    int excl = ws[w] + inc - v;
    if (idx < NN) d_offs[idx] = excl;
    if (t == 1023) d_bsum[blockIdx.x] = excl + v;
}

__global__ __launch_bounds__(1024) void k_scan2() {
    __shared__ int bp[11];
    if (threadIdx.x == 0) {
        int s = 0;
#pragma unroll
        for (int b = 0; b < 10; b++) { bp[b] = s; s += d_bsum[b]; }
        d_offs[NN] = s;
    }
    __syncthreads();
    for (int idx = threadIdx.x; idx < NN; idx += 1024) {
        int o = d_offs[idx] + bp[idx >> 10];
        d_offs[idx] = o;
        d_cursor[idx] = o;
    }
}

__global__ void k_scatter(const int* __restrict__ ei) {
    int e = blockIdx.x * blockDim.x + threadIdx.x;
    if (e >= EE) return;
    if (!d_act[e]) return;
    int rv = ei[EE + e];
    int p = atomicAdd(&d_cursor[rv], 1);
    d_sedge[p] = make_int2(e, ei[e]);
}

// ---------------- agg: tensor-core tp_w + fused message/segment-sum ----------------
__global__ __launch_bounds__(128) void k_agg(int t) {
    __shared__ float aggS[8 * 576];
    __shared__ __half W2S[576 * 16];
    __shared__ __half zS[16][16];
    __shared__ float hupS[16][64];
    __shared__ float shS[16][12];
    __shared__ int rowNode[16];
    __shared__ int sndS[16];
    __shared__ int offsS[9];
    int tid = threadIdx.x, lane = tid & 31, w = tid >> 5;
    int n0 = blockIdx.x * 8;
    {
        const uint4* src = (const uint4*)d_W2T[t];
        uint4* dst = (uint4*)W2S;
#pragma unroll
        for (int i = 0; i < 9; i++) dst[tid + i * 128] = src[tid + i * 128];
    }
    if (tid < 9) offsS[tid] = d_offs[n0 + tid];
    for (int i = tid; i < 8 * 576; i += 128) aggS[i] = 0.f;
    __syncthreads();
    int i0 = offsS[0], i1 = offsS[8];

    for (int base = i0; base < i1; base += 16) {
        int cnt = min(16, i1 - base);
        if (tid < 16) {
            int r = tid;
            if (r < cnt) {
                int2 es = d_sedge[base + r];
                int ln = 0;
#pragma unroll
                for (int q = 1; q < 8; q++) if (base + r >= offsS[q]) ln = q;
                rowNode[r] = ln; sndS[r] = es.y;
                const uint4* zp = (const uint4*)&d_zh[t][(long)es.x * 16];
                ((uint4*)zS[r])[0] = zp[0];
                ((uint4*)zS[r])[1] = zp[1];
                const float4* sp = (const float4*)&d_sh12[(long)es.x * 12];
                ((float4*)shS[r])[0] = sp[0];
                ((float4*)shS[r])[1] = sp[1];
                ((float4*)shS[r])[2] = sp[2];
            } else {
                rowNode[r] = 0; sndS[r] = -1;
                uint4 z0 = make_uint4(0, 0, 0, 0);
                ((uint4*)zS[r])[0] = z0;
                ((uint4*)zS[r])[1] = z0;
                float4 f0 = make_float4(0.f, 0.f, 0.f, 0.f);
                ((float4*)shS[r])[0] = f0;
                ((float4*)shS[r])[1] = f0;
                ((float4*)shS[r])[2] = f0;
            }
        }
        __syncthreads();
        {
            int r = tid >> 3, cq = tid & 7;
            int sn = sndS[r];
            float4 a = make_float4(0.f, 0.f, 0.f, 0.f), b = a;
            if (sn >= 0) {
                const float4* hp = (const float4*)&d_hup[sn * 64 + cq * 8];
                a = hp[0]; b = hp[1];
            }
            *(float4*)&hupS[r][cq * 8] = a;
            *(float4*)&hupS[r][cq * 8 + 4] = b;
        }
        __syncthreads();

        int ar = lane >> 2, ak = (lane & 3) * 2;
        unsigned A0 = *(const unsigned*)&zS[ar][ak];
        unsigned A1 = *(const unsigned*)&zS[ar + 8][ak];
        unsigned A2 = *(const unsigned*)&zS[ar][ak + 8];
        unsigned A3 = *(const unsigned*)&zS[ar + 8][ak + 8];
#pragma unroll
        for (int q = 0; q < 18; q++) {
            int cb = (w * 18 + q) * 8;
            unsigned B0 = *(const unsigned*)&W2S[(cb + ar) * 16 + ak];
            unsigned B1 = *(const unsigned*)&W2S[(cb + ar) * 16 + ak + 8];
            float c0 = 0.f, c1 = 0.f, c2 = 0.f, c3 = 0.f;
            mma16816(c0, c1, c2, c3, A0, A1, A2, A3, B0, B1);
            int cg0 = cb + 2 * (lane & 3);
            int cc0 = (cg0 * 7282) >> 16; int ss0 = cg0 - cc0 * 9;
            int cg1 = cg0 + 1;
            int cc1 = (cg1 * 7282) >> 16; int ss1 = cg1 - cc1 * 9;
            int rA = ar, rB = ar + 8;
            int nA = rowNode[rA], nB = rowNode[rB];
            atomicAdd(&aggS[nA * 576 + cg0], c0 * hupS[rA][cc0] * shS[rA][ss0]);
            atomicAdd(&aggS[nA * 576 + cg1], c1 * hupS[rA][cc1] * shS[rA][ss1]);
            atomicAdd(&aggS[nB * 576 + cg0], c2 * hupS[rB][cc0] * shS[rB][ss0]);
            atomicAdd(&aggS[nB * 576 + cg1], c3 * hupS[rB][cc1] * shS[rB][ss1]);
        }
        __syncthreads();
    }
    {
        __half2* dst = (__half2*)&d_aggh[(long)n0 * 576];
        for (int i = tid; i < 8 * 576 / 2; i += 128) {
            dst[i] = __floats2half2_rn(aggS[2 * i] * (1.f / 32.f), aggS[2 * i + 1] * (1.f / 32.f));
        }
    }
}

// ---------------- update: fp16 MMA GEMM + fused epilogues ----------------
__global__ __launch_bounds__(128) void k_update(int t, const float* __restrict__ wread,
                                                const float* __restrict__ Wmlp1,
                                                const float* __restrict__ wmlp2,
                                                float* __restrict__ out) {
    __shared__ __half As[64][16];
    __shared__ __half BsT[64][16];
    __shared__ __half hS[64][72];
    __shared__ __half WuS[64 * 64];
    int tid = threadIdx.x, lane = tid & 31, w = tid >> 5;
    int m0 = blockIdx.x * 64;
    float C[8][4];
#pragma unroll
    for (int j = 0; j < 8; j++)
#pragma unroll
        for (int i = 0; i < 4; i++) C[j][i] = 0.f;

    int r = tid >> 1, hf = tid & 1;
    int node = m0 + r;
    int arf = 16 * w + (lane >> 2), akf = (lane & 3) * 2;

    for (int step = 0; step < 40; step++) {
        int k0 = step * 16;
        uint4 av = make_uint4(0, 0, 0, 0);
        if (node < NN) {
            const uint4* ap = (k0 < 576) ? (const uint4*)&d_aggh[(long)node * 576 + k0]
                                         : (const uint4*)&d_hh[node * 64 + (k0 - 576)];
            av = ap[hf];
        }
        uint4 bv = *((const uint4*)&d_BT[t][r * 640 + k0] + hf);
        __syncthreads();
        *(uint4*)&As[r][hf * 8] = av;
        *(uint4*)&BsT[r][hf * 8] = bv;
        __syncthreads();
        unsigned A0 = *(const unsigned*)&As[arf][akf];
        unsigned A1 = *(const unsigned*)&As[arf + 8][akf];
        unsigned A2 = *(const unsigned*)&As[arf][akf + 8];
        unsigned A3 = *(const unsigned*)&As[arf + 8][akf + 8];
#pragma unroll
        for (int j = 0; j < 8; j++) {
            int bn = j * 8 + (lane >> 2);
            unsigned B0 = *(const unsigned*)&BsT[bn][akf];
            unsigned B1 = *(const unsigned*)&BsT[bn][akf + 8];
            mma16816(C[j][0], C[j][1], C[j][2], C[j][3], A0, A1, A2, A3, B0, B1);
        }
    }
    __syncthreads();
    {   // C fragments -> hS (half)
        int ac = 2 * (lane & 3);
#pragma unroll
        for (int j = 0; j < 8; j++) {
            *(__half2*)&hS[arf][j * 8 + ac]     = __floats2half2_rn(C[j][0], C[j][1]);
            *(__half2*)&hS[arf + 8][j * 8 + ac] = __floats2half2_rn(C[j][2], C[j][3]);
        }
    }
    __syncthreads();

    if (t == 0) {
        // write h1 (half) for next layer's update
        for (int i = tid; i < 64 * 32; i += 128) {
            int rr = i >> 5, cc2 = i & 31;
            if (m0 + rr < NN)
                ((__half2*)&d_hh[(m0 + rr) * 64])[cc2] = *(__half2*)&hS[rr][cc2 * 2];
        }
        // read1 = h1 @ w_read
        if (tid < 64 && m0 + tid < NN) {
            float acc = 0.f;
#pragma unroll
            for (int k2 = 0; k2 < 64; k2++)
                acc = fmaf(__half2float(hS[tid][k2]), wread[k2], acc);
            out[NN + m0 + tid] = acc;
        }
        // stage W_up[1]^T
        {
            const uint4* src = (const uint4*)d_WupT;
            uint4* dst = (uint4*)WuS;
#pragma unroll
            for (int i = 0; i < 4; i++) dst[tid + i * 128] = src[tid + i * 128];
        }
        __syncthreads();
        // hup1 = h1 @ W_up[1] via MMA
        float H[8][4];
#pragma unroll
        for (int j = 0; j < 8; j++)
#pragma unroll
            for (int i = 0; i < 4; i++) H[j][i] = 0.f;
#pragma unroll
        for (int s = 0; s < 4; s++) {
            int k0 = s * 16;
            unsigned A0 = *(const unsigned*)&hS[arf][k0 + akf];
            unsigned A1 = *(const unsigned*)&hS[arf + 8][k0 + akf];
            unsigned A2 = *(const unsigned*)&hS[arf][k0 + akf + 8];
            unsigned A3 = *(const unsigned*)&hS[arf + 8][k0 + akf + 8];
#pragma unroll
            for (int j = 0; j < 8; j++) {
                int bn = j * 8 + (lane >> 2);
                unsigned B0 = *(const unsigned*)&WuS[bn * 64 + k0 + akf];
                unsigned B1 = *(const unsigned*)&WuS[bn * 64 + k0 + akf + 8];
                mma16816(H[j][0], H[j][1], H[j][2], H[j][3], A0, A1, A2, A3, B0, B1);
            }
        }
        int ac = 2 * (lane & 3);
#pragma unroll
        for (int j = 0; j < 8; j++) {
            int col = j * 8 + ac;
            if (m0 + arf < NN) {
                d_hup[(m0 + arf) * 64 + col] = H[j][0];
                d_hup[(m0 + arf) * 64 + col + 1] = H[j][1];
            }
            if (m0 + arf + 8 < NN) {
                d_hup[(m0 + arf + 8) * 64 + col] = H[j][2];
                d_hup[(m0 + arf + 8) * 64 + col + 1] = H[j][3];
            }
        }
    } else {
        // read2 = silu(h2 @ W_mlp1) @ w_mlp2 ; 2 threads per node
        int nd = tid >> 1, hf2 = tid & 1;
        float y[8];
#pragma unroll
        for (int o = 0; o < 8; o++) y[o] = 0.f;
        for (int k2 = 0; k2 < 64; k2++) {
            float hv = __half2float(hS[nd][k2]);
#pragma unroll
            for (int o = 0; o < 8; o++)
                y[o] = fmaf(hv, Wmlp1[k2 * 16 + hf2 * 8 + o], y[o]);
        }
        float acc = 0.f;
#pragma unroll
        for (int o = 0; o < 8; o++) {
            float s2 = __fdividef(y[o], 1.0f + __expf(-y[o]));
            acc = fmaf(s2, wmlp2[hf2 * 8 + o], acc);
        }
        acc += __shfl_xor_sync(0xffffffffu, acc, 1);
        if (hf2 == 0 && m0 + nd < NN) out[2 * NN + m0 + nd] = acc;
    }
}

// ---------------- host launch ----------------
extern "C" void kernel_launch(void* const* d_in, const int* in_sizes, int n_in,
                              void* d_out, int out_size) {
    const float *positions = nullptr, *node_attrs = nullptr, *shifts = nullptr;
    const float *atomic_energies = nullptr, *W_embed = nullptr, *W_up = nullptr;
    const float *W_r1 = nullptr, *W_r2 = nullptr, *W_mix = nullptr, *W_self = nullptr;
    const float *w_read = nullptr, *W_mlp1 = nullptr, *w_mlp2 = nullptr;
    const int* edge_index = nullptr;
    for (int i = 0; i < n_in; i++) {
        switch (in_sizes[i]) {
            case 30000:  positions = (const float*)d_in[i]; break;
            case 100000: node_attrs = (const float*)d_in[i]; break;
            case 480000: shifts = (const float*)d_in[i]; break;
            case 320000: edge_index = (const int*)d_in[i]; break;
            case 10:     atomic_energies = (const float*)d_in[i]; break;
            case 640:    W_embed = (const float*)d_in[i]; break;
            case 8192:   if (!W_up) W_up = (const float*)d_in[i];
                         else W_self = (const float*)d_in[i]; break;
            case 256:    W_r1 = (const float*)d_in[i]; break;
            case 18432:  W_r2 = (const float*)d_in[i]; break;
            case 73728:  W_mix = (const float*)d_in[i]; break;
            case 64:     w_read = (const float*)d_in[i]; break;
            case 1024:   W_mlp1 = (const float*)d_in[i]; break;
            case 16:     w_mlp2 = (const float*)d_in[i]; break;
            default: break;
        }
    }
    float* out = (float*)d_out;
    (void)out_size;

    k_prep<<<(18432 + 81920 + 4096 + 255) / 256, 256>>>(W_r2, W_mix, W_self, W_up);
    k_embed<<<NN, 64>>>(node_attrs, W_embed, atomic_energies, W_up, out);
    k_geom<<<(EE + 255) / 256, 256>>>(positions, shifts, edge_index, W_r1);
    k_scan1<<<10, 1024>>>();
    k_scan2<<<1, 1024>>>();
    k_scatter<<<(EE + 255) / 256, 256>>>(edge_index);

    for (int t = 0; t < 2; t++) {
        k_agg<<<NN / 8, 128>>>(t);
        k_update<<<(NN + 63) / 64, 128>>>(t, w_read, W_mlp1, w_mlp2, out);
    }
}

// round 5
// speedup vs baseline: 2.2725x; 2.2725x over previous
#include <cuda_runtime.h>
#include <cuda_fp16.h>
#include <math.h>

#define NN 10000
#define EE 160000
#define CC 64
#define RMAXF 5.0f
#define NPB 16

// ---------------- device scratch ----------------
__device__ float4 d_vec[EE];           // (vx,vy,vz,r) for active edges
__device__ float d_sh12[EE * 12];      // slot-indexed sh (9 used, pad 12)
__device__ float d_z[2][EE * 16];      // slot-indexed silu(radial@W_r1)
__device__ unsigned char d_act[EE];
__device__ int   d_count[NN];          // zero-init; self-restored by k_scan1
__device__ int   d_offs[NN + 1];
__device__ int   d_cursor[NN];
__device__ int2  d_sedge[EE];          // (edge id, sender id) per sorted slot
__device__ int   d_bsum[16];
__device__ float d_hup[NN * CC];
__device__ __half d_hh[NN * CC];
__device__ __half d_aggh[NN * 576];
__device__ __half d_BT[2][64 * 640];   // [n][k] for update GEMM
__device__ __half d_WupT[64 * 64];     // W_up[1] transposed [o][i]

__device__ __forceinline__ void mma16816(float& c0, float& c1, float& c2, float& c3,
                                         unsigned a0, unsigned a1, unsigned a2, unsigned a3,
                                         unsigned b0, unsigned b1) {
    asm volatile(
        "mma.sync.aligned.m16n8k16.row.col.f32.f16.f16.f32 "
        "{%0,%1,%2,%3},{%4,%5,%6,%7},{%8,%9},{%0,%1,%2,%3};\n"
        : "+f"(c0), "+f"(c1), "+f"(c2), "+f"(c3)
        : "r"(a0), "r"(a1), "r"(a2), "r"(a3), "r"(b0), "r"(b1));
}

// ---------------- weight prep ----------------
__global__ void k_prep(const float* __restrict__ Wmix, const float* __restrict__ Wself,
                       const float* __restrict__ Wup) {
    int i = blockIdx.x * 256 + threadIdx.x;
    if (i < 2 * 40960) {
        int t = i / 40960, r = i - t * 40960, n = r / 640, k = r - n * 640;
        float v = (k < 576) ? Wmix[t * 36864 + k * 64 + n] : Wself[t * 4096 + (k - 576) * 64 + n];
        d_BT[t][r] = __float2half(v);
    }
    int q = i - 81920;
    if (q >= 0 && q < 4096) {
        int o = q >> 6, ii = q & 63;
        d_WupT[q] = __float2half(Wup[4096 + ii * 64 + o]);
    }
}

// ---------------- embed: h0(half), hup0, out row0 ----------------
__global__ __launch_bounds__(64) void k_embed(const float* __restrict__ na,
                        const float* __restrict__ We, const float* __restrict__ ae,
                        const float* __restrict__ Wup, float* __restrict__ out) {
    __shared__ float hs[64];
    int n = blockIdx.x, c = threadIdx.x;
    float acc = 0.f;
#pragma unroll
    for (int k = 0; k < 10; k++) acc = fmaf(na[n * 10 + k], We[k * 64 + c], acc);
    hs[c] = acc;
    d_hh[n * 64 + c] = __float2half(acc);
    if (c == 0) {
        float r = 0.f;
#pragma unroll
        for (int k = 0; k < 10; k++) r = fmaf(na[n * 10 + k], ae[k], r);
        out[n] = r;
    }
    __syncthreads();
    float hu = 0.f;
#pragma unroll
    for (int k = 0; k < 64; k++) hu = fmaf(hs[k], Wup[k * 64 + c], hu);
    d_hup[n * 64 + c] = hu;
}

// ---------------- geom pass 1: cheap distance/activity over all edges ----------------
__global__ __launch_bounds__(256) void k_geom1(const float* __restrict__ pos,
                       const float* __restrict__ shifts, const int* __restrict__ ei) {
    int e = blockIdx.x * blockDim.x + threadIdx.x;
    if (e >= EE) return;
    int s  = ei[e];
    int rv = ei[EE + e];
    float vx = pos[rv * 3 + 0] - pos[s * 3 + 0] + shifts[e * 3 + 0];
    float vy = pos[rv * 3 + 1] - pos[s * 3 + 1] + shifts[e * 3 + 1];
    float vz = pos[rv * 3 + 2] - pos[s * 3 + 2] + shifts[e * 3 + 2];
    float r = sqrtf(vx * vx + vy * vy + vz * vz) + 1e-9f;
    bool act = (r < RMAXF);
    d_act[e] = act ? 1 : 0;
    if (!act) return;
    atomicAdd(&d_count[rv], 1);
    d_vec[e] = make_float4(vx, vy, vz, r);
}

// ---------------- scan (2 kernels) + scatter ----------------
__global__ __launch_bounds__(1024) void k_scan1() {
    __shared__ int ws[32];
    int t = threadIdx.x, lane = t & 31, w = t >> 5;
    int idx = blockIdx.x * 1024 + t;
    int v = 0;
    if (idx < NN) { v = d_count[idx]; d_count[idx] = 0; }
    int inc = v;
#pragma unroll
    for (int o = 1; o < 32; o <<= 1) {
        int u = __shfl_up_sync(0xffffffffu, inc, o);
        if (lane >= o) inc += u;
    }
    if (lane == 31) ws[w] = inc;
    __syncthreads();
    if (w == 0) {
        int x = ws[lane];
        int xi = x;
#pragma unroll
        for (int o = 1; o < 32; o <<= 1) {
            int u = __shfl_up_sync(0xffffffffu, xi, o);
            if (lane >= o) xi += u;
        }
        ws[lane] = xi - x;
    }
    __syncthreads();
    int excl = ws[w] + inc - v;
    if (idx < NN) d_offs[idx] = excl;
    if (t == 1023) d_bsum[blockIdx.x] = excl + v;
}

__global__ __launch_bounds__(1024) void k_scan2() {
    __shared__ int bp[11];
    if (threadIdx.x == 0) {
        int s = 0;
#pragma unroll
        for (int b = 0; b < 10; b++) { bp[b] = s; s += d_bsum[b]; }
        d_offs[NN] = s;
    }
    __syncthreads();
    for (int idx = threadIdx.x; idx < NN; idx += 1024) {
        int o = d_offs[idx] + bp[idx >> 10];
        d_offs[idx] = o;
        d_cursor[idx] = o;
    }
}

__global__ void k_scatter(const int* __restrict__ ei) {
    int e = blockIdx.x * blockDim.x + threadIdx.x;
    if (e >= EE) return;
    if (!d_act[e]) return;
    int rv = ei[EE + e];
    int p = atomicAdd(&d_cursor[rv], 1);
    d_sedge[p] = make_int2(e, ei[e]);
}

// ---------------- geom pass 2: heavy sh/radial/silu over compacted slots ----------------
__global__ __launch_bounds__(256) void k_geom2(const float* __restrict__ Wr1) {
    __shared__ float Ws[256];
    Ws[threadIdx.x] = Wr1[threadIdx.x];
    __syncthreads();
    int i = blockIdx.x * blockDim.x + threadIdx.x;
    if (i >= d_offs[NN]) return;
    int e = d_sedge[i].x;
    float4 v = d_vec[e];
    float r = v.w;
    float inv = __fdividef(1.0f, r);
    float ux = v.x * inv, uy = v.y * inv, uz = v.z * inv;
    const float s3 = 1.7320508075688772f, s5 = 2.2360679774997896f, s15 = 3.872983346207417f;
    float4 fA = make_float4(1.0f, s3 * ux, s3 * uy, s3 * uz);
    float4 fB = make_float4(s15 * ux * uy, s15 * uy * uz,
                            0.5f * s5 * (3.0f * uz * uz - 1.0f), s15 * ux * uz);
    float4 fC = make_float4(0.5f * s15 * (ux * ux - uy * uy), 0.f, 0.f, 0.f);
    float4* shp = (float4*)&d_sh12[(long)i * 12];
    shp[0] = fA; shp[1] = fB; shp[2] = fC;

    float xx = r * (1.0f / RMAXF);
    float th = 3.14159265358979323846f * xx;
    float s1, c1;
    __sincosf(th, &s1, &c1);
    float x2 = xx * xx;
    float x6 = x2 * x2 * x2;
    float fc = 1.0f + x6 * (-28.0f + xx * (48.0f - 21.0f * xx));
    float pref = 0.6324555320336759f * inv * fc;
    float ef[8];
    float sp = 0.0f, sc = s1, c2 = 2.0f * c1;
#pragma unroll
    for (int n = 0; n < 8; n++) {
        ef[n] = pref * sc;
        float nx = c2 * sc - sp;
        sp = sc; sc = nx;
    }
#pragma unroll
    for (int t = 0; t < 2; t++) {
        float a[16];
#pragma unroll
        for (int m = 0; m < 16; m++) {
            float acc = 0.f;
#pragma unroll
            for (int n = 0; n < 8; n++) acc = fmaf(ef[n], Ws[t * 128 + n * 16 + m], acc);
            a[m] = __fdividef(acc, 1.0f + __expf(-acc));
        }
        float4* zp = (float4*)&d_z[t][(long)i * 16];
#pragma unroll
        for (int q = 0; q < 4; q++)
            zp[q] = make_float4(a[q * 4], a[q * 4 + 1], a[q * 4 + 2], a[q * 4 + 3]);
    }
}

// ---------------- agg: scalar (round-3 style), slot-indexed, half output ----------------
template<int SOFF, int SCNT>
__device__ __forceinline__ void agg_body(int c, int n0, int n1,
                                         const float* __restrict__ z,
                                         const float* __restrict__ Wr2) {
    float W[16][SCNT];
#pragma unroll
    for (int m = 0; m < 16; m++)
#pragma unroll
        for (int j = 0; j < SCNT; j++) W[m][j] = Wr2[m * 576 + c * 9 + SOFF + j];
    for (int n = n0; n < n1; n++) {
        float acc[SCNT];
#pragma unroll
        for (int j = 0; j < SCNT; j++) acc[j] = 0.f;
        int b = d_offs[n], e1 = d_offs[n + 1];
        for (int i = b; i < e1; i++) {
            float hv = d_hup[d_sedge[i].y * CC + c];
            const float4* z4 = (const float4*)&z[(long)i * 16];
            float4 za = z4[0], zb = z4[1], zc = z4[2], zd = z4[3];
            float zz[16] = {za.x, za.y, za.z, za.w, zb.x, zb.y, zb.z, zb.w,
                            zc.x, zc.y, zc.z, zc.w, zd.x, zd.y, zd.z, zd.w};
            float shv[SCNT];
            if (SOFF == 0) {
                float4 sA = *(const float4*)&d_sh12[(long)i * 12];
                shv[0] = sA.x; shv[1] = sA.y; shv[2] = sA.z; shv[3] = sA.w;
                shv[4] = d_sh12[(long)i * 12 + 4];
            } else {
                float4 sB = *(const float4*)&d_sh12[(long)i * 12 + 4];
                shv[0] = sB.y; shv[1] = sB.z; shv[2] = sB.w;
                shv[3] = d_sh12[(long)i * 12 + 8];
            }
            float ws[SCNT];
#pragma unroll
            for (int j = 0; j < SCNT; j++) ws[j] = 0.f;
#pragma unroll
            for (int m = 0; m < 16; m++)
#pragma unroll
                for (int j = 0; j < SCNT; j++) ws[j] = fmaf(zz[m], W[m][j], ws[j]);
#pragma unroll
            for (int j = 0; j < SCNT; j++) acc[j] = fmaf(hv * shv[j], ws[j], acc[j]);
        }
#pragma unroll
        for (int j = 0; j < SCNT; j++)
            d_aggh[(long)n * 576 + c * 9 + SOFF + j] = __float2half(acc[j] * (1.0f / 32.0f));
    }
}

__global__ __launch_bounds__(128) void k_agg(int t, const float* __restrict__ Wr2) {
    int c = threadIdx.x & 63;
    int half_ = threadIdx.x >> 6;
    int n0 = blockIdx.x * NPB;
    int n1 = n0 + NPB; if (n1 > NN) n1 = NN;
    const float* z = d_z[t];
    if (half_ == 0) agg_body<0, 5>(c, n0, n1, z, Wr2);
    else            agg_body<5, 4>(c, n0, n1, z, Wr2);
}

// ---------------- update: fp16 MMA GEMM + fused epilogues ----------------
__global__ __launch_bounds__(128) void k_update(int t, const float* __restrict__ wread,
                                                const float* __restrict__ Wmlp1,
                                                const float* __restrict__ wmlp2,
                                                float* __restrict__ out) {
    __shared__ __half As[64][16];
    __shared__ __half BsT[64][16];
    __shared__ __half hS[64][72];
    __shared__ __half WuS[64 * 64];
    int tid = threadIdx.x, lane = tid & 31, w = tid >> 5;
    int m0 = blockIdx.x * 64;
    float C[8][4];
#pragma unroll
    for (int j = 0; j < 8; j++)
#pragma unroll
        for (int i = 0; i < 4; i++) C[j][i] = 0.f;

    int r = tid >> 1, hf = tid & 1;
    int node = m0 + r;
    int arf = 16 * w + (lane >> 2), akf = (lane & 3) * 2;

    for (int step = 0; step < 40; step++) {
        int k0 = step * 16;
        uint4 av = make_uint4(0, 0, 0, 0);
        if (node < NN) {
            const uint4* ap = (k0 < 576) ? (const uint4*)&d_aggh[(long)node * 576 + k0]
                                         : (const uint4*)&d_hh[node * 64 + (k0 - 576)];
            av = ap[hf];
        }
        uint4 bv = *((const uint4*)&d_BT[t][r * 640 + k0] + hf);
        __syncthreads();
        *(uint4*)&As[r][hf * 8] = av;
        *(uint4*)&BsT[r][hf * 8] = bv;
        __syncthreads();
        unsigned A0 = *(const unsigned*)&As[arf][akf];
        unsigned A1 = *(const unsigned*)&As[arf + 8][akf];
        unsigned A2 = *(const unsigned*)&As[arf][akf + 8];
        unsigned A3 = *(const unsigned*)&As[arf + 8][akf + 8];
#pragma unroll
        for (int j = 0; j < 8; j++) {
            int bn = j * 8 + (lane >> 2);
            unsigned B0 = *(const unsigned*)&BsT[bn][akf];
            unsigned B1 = *(const unsigned*)&BsT[bn][akf + 8];
            mma16816(C[j][0], C[j][1], C[j][2], C[j][3], A0, A1, A2, A3, B0, B1);
        }
    }
    __syncthreads();
    {
        int ac = 2 * (lane & 3);
#pragma unroll
        for (int j = 0; j < 8; j++) {
            *(__half2*)&hS[arf][j * 8 + ac]     = __floats2half2_rn(C[j][0], C[j][1]);
            *(__half2*)&hS[arf + 8][j * 8 + ac] = __floats2half2_rn(C[j][2], C[j][3]);
        }
    }
    __syncthreads();

    if (t == 0) {
        for (int i = tid; i < 64 * 32; i += 128) {
            int rr = i >> 5, cc2 = i & 31;
            if (m0 + rr < NN)
                ((__half2*)&d_hh[(m0 + rr) * 64])[cc2] = *(__half2*)&hS[rr][cc2 * 2];
        }
        if (tid < 64 && m0 + tid < NN) {
            float acc = 0.f;
#pragma unroll
            for (int k2 = 0; k2 < 64; k2++)
                acc = fmaf(__half2float(hS[tid][k2]), wread[k2], acc);
            out[NN + m0 + tid] = acc;
        }
        {
            const uint4* src = (const uint4*)d_WupT;
            uint4* dst = (uint4*)WuS;
#pragma unroll
            for (int i = 0; i < 4; i++) dst[tid + i * 128] = src[tid + i * 128];
        }
        __syncthreads();
        float H[8][4];
#pragma unroll
        for (int j = 0; j < 8; j++)
#pragma unroll
            for (int i = 0; i < 4; i++) H[j][i] = 0.f;
#pragma unroll
        for (int s = 0; s < 4; s++) {
            int k0 = s * 16;
            unsigned A0 = *(const unsigned*)&hS[arf][k0 + akf];
            unsigned A1 = *(const unsigned*)&hS[arf + 8][k0 + akf];
            unsigned A2 = *(const unsigned*)&hS[arf][k0 + akf + 8];
            unsigned A3 = *(const unsigned*)&hS[arf + 8][k0 + akf + 8];
#pragma unroll
            for (int j = 0; j < 8; j++) {
                int bn = j * 8 + (lane >> 2);
                unsigned B0 = *(const unsigned*)&WuS[bn * 64 + k0 + akf];
                unsigned B1 = *(const unsigned*)&WuS[bn * 64 + k0 + akf + 8];
                mma16816(H[j][0], H[j][1], H[j][2], H[j][3], A0, A1, A2, A3, B0, B1);
            }
        }
        int ac = 2 * (lane & 3);
#pragma unroll
        for (int j = 0; j < 8; j++) {
            int col = j * 8 + ac;
            if (m0 + arf < NN) {
                d_hup[(m0 + arf) * 64 + col] = H[j][0];
                d_hup[(m0 + arf) * 64 + col + 1] = H[j][1];
            }
            if (m0 + arf + 8 < NN) {
                d_hup[(m0 + arf + 8) * 64 + col] = H[j][2];
                d_hup[(m0 + arf + 8) * 64 + col + 1] = H[j][3];
            }
        }
    } else {
        int nd = tid >> 1, hf2 = tid & 1;
        float y[8];
#pragma unroll
        for (int o = 0; o < 8; o++) y[o] = 0.f;
        for (int k2 = 0; k2 < 64; k2++) {
            float hv = __half2float(hS[nd][k2]);
#pragma unroll
            for (int o = 0; o < 8; o++)
                y[o] = fmaf(hv, Wmlp1[k2 * 16 + hf2 * 8 + o], y[o]);
        }
        float acc = 0.f;
#pragma unroll
        for (int o = 0; o < 8; o++) {
            float s2 = __fdividef(y[o], 1.0f + __expf(-y[o]));
            acc = fmaf(s2, wmlp2[hf2 * 8 + o], acc);
        }
        acc += __shfl_xor_sync(0xffffffffu, acc, 1);
        if (hf2 == 0 && m0 + nd < NN) out[2 * NN + m0 + nd] = acc;
    }
}

// ---------------- host launch ----------------
extern "C" void kernel_launch(void* const* d_in, const int* in_sizes, int n_in,
                              void* d_out, int out_size) {
    const float *positions = nullptr, *node_attrs = nullptr, *shifts = nullptr;
    const float *atomic_energies = nullptr, *W_embed = nullptr, *W_up = nullptr;
    const float *W_r1 = nullptr, *W_r2 = nullptr, *W_mix = nullptr, *W_self = nullptr;
    const float *w_read = nullptr, *W_mlp1 = nullptr, *w_mlp2 = nullptr;
    const int* edge_index = nullptr;
    for (int i = 0; i < n_in; i++) {
        switch (in_sizes[i]) {
            case 30000:  positions = (const float*)d_in[i]; break;
            case 100000: node_attrs = (const float*)d_in[i]; break;
            case 480000: shifts = (const float*)d_in[i]; break;
            case 320000: edge_index = (const int*)d_in[i]; break;
            case 10:     atomic_energies = (const float*)d_in[i]; break;
            case 640:    W_embed = (const float*)d_in[i]; break;
            case 8192:   if (!W_up) W_up = (const float*)d_in[i];
                         else W_self = (const float*)d_in[i]; break;
            case 256:    W_r1 = (const float*)d_in[i]; break;
            case 18432:  W_r2 = (const float*)d_in[i]; break;
            case 73728:  W_mix = (const float*)d_in[i]; break;
            case 64:     w_read = (const float*)d_in[i]; break;
            case 1024:   W_mlp1 = (const float*)d_in[i]; break;
            case 16:     w_mlp2 = (const float*)d_in[i]; break;
            default: break;
        }
    }
    float* out = (float*)d_out;
    (void)out_size;

    k_prep<<<(81920 + 4096 + 255) / 256, 256>>>(W_mix, W_self, W_up);
    k_embed<<<NN, 64>>>(node_attrs, W_embed, atomic_energies, W_up, out);
    k_geom1<<<(EE + 255) / 256, 256>>>(positions, shifts, edge_index);
    k_scan1<<<10, 1024>>>();
    k_scan2<<<1, 1024>>>();
    k_scatter<<<(EE + 255) / 256, 256>>>(edge_index);
    k_geom2<<<(EE + 255) / 256, 256>>>(W_r1);

    for (int t = 0; t < 2; t++) {
        k_agg<<<(NN + NPB - 1) / NPB, 128>>>(t, W_r2 + t * 16 * 576);
        k_update<<<(NN + 63) / 64, 128>>>(t, w_read, W_mlp1, w_mlp2, out);
    }
}

// round 6
// speedup vs baseline: 2.5541x; 1.1239x over previous
#include <cuda_runtime.h>
#include <cuda_fp16.h>
#include <math.h>

#define NN 10000
#define EE 160000
#define CC 64
#define RMAXF 5.0f
#define NPB 8

#define GEOM_BLKS 625
#define EMB_BLKS  5000
#define PREP_BLKS 672
#define SETUP_BLKS (GEOM_BLKS + EMB_BLKS + PREP_BLKS)

// ---------------- device scratch ----------------
__device__ float4 d_vec[EE];           // (vx,vy,vz,r) for active edges
__device__ float d_sh12[EE * 12];      // slot-indexed sh (9 used, pad 12)
__device__ float d_z[2][EE * 16];      // slot-indexed silu(radial@W_r1)
__device__ unsigned char d_act[EE];
__device__ int   d_count[NN];          // zero-init; self-restored by k_scan
__device__ int   d_offs[NN + 1];
__device__ int   d_cursor[NN];
__device__ int   d_ssnd[EE];           // sender id per sorted slot
__device__ float d_hup[NN * CC];
__device__ __half d_hh[NN * CC];
__device__ __half d_aggh[NN * 576];
__device__ __half d_BT[2][64 * 640];   // [n][k] for update GEMM
__device__ __half d_WupT[64 * 64];     // W_up[1] transposed [o][i]

__device__ __forceinline__ void mma16816(float& c0, float& c1, float& c2, float& c3,
                                         unsigned a0, unsigned a1, unsigned a2, unsigned a3,
                                         unsigned b0, unsigned b1) {
    asm volatile(
        "mma.sync.aligned.m16n8k16.row.col.f32.f16.f16.f32 "
        "{%0,%1,%2,%3},{%4,%5,%6,%7},{%8,%9},{%0,%1,%2,%3};\n"
        : "+f"(c0), "+f"(c1), "+f"(c2), "+f"(c3)
        : "r"(a0), "r"(a1), "r"(a2), "r"(a3), "r"(b0), "r"(b1));
}

// ---------------- fused setup: geom1 | embed | weight prep ----------------
__device__ __forceinline__ void geom1_edge(int e, const float* __restrict__ pos,
                                           const float* __restrict__ shifts,
                                           const int* __restrict__ ei) {
    int s  = ei[e];
    int rv = ei[EE + e];
    float vx = pos[rv * 3 + 0] - pos[s * 3 + 0] + shifts[e * 3 + 0];
    float vy = pos[rv * 3 + 1] - pos[s * 3 + 1] + shifts[e * 3 + 1];
    float vz = pos[rv * 3 + 2] - pos[s * 3 + 2] + shifts[e * 3 + 2];
    float r = sqrtf(vx * vx + vy * vy + vz * vz) + 1e-9f;
    bool act = (r < RMAXF);
    d_act[e] = act ? 1 : 0;
    if (!act) return;
    atomicAdd(&d_count[rv], 1);
    d_vec[e] = make_float4(vx, vy, vz, r);
}

__global__ __launch_bounds__(128) void k_setup(const float* __restrict__ pos,
        const float* __restrict__ shifts, const int* __restrict__ ei,
        const float* __restrict__ na, const float* __restrict__ We,
        const float* __restrict__ ae, const float* __restrict__ Wup,
        const float* __restrict__ Wmix, const float* __restrict__ Wself,
        float* __restrict__ out) {
    int b = blockIdx.x, tid = threadIdx.x;
    if (b < GEOM_BLKS) {
        int e0 = b * 256 + tid;
        geom1_edge(e0, pos, shifts, ei);
        geom1_edge(e0 + 128, pos, shifts, ei);
    } else if (b < GEOM_BLKS + EMB_BLKS) {
        __shared__ float hs[128];
        int slot = tid >> 6, c = tid & 63;
        int n = (b - GEOM_BLKS) * 2 + slot;
        float acc = 0.f;
#pragma unroll
        for (int k = 0; k < 10; k++) acc = fmaf(na[n * 10 + k], We[k * 64 + c], acc);
        hs[tid] = acc;
        d_hh[n * 64 + c] = __float2half(acc);
        if (c == 0) {
            float r = 0.f;
#pragma unroll
            for (int k = 0; k < 10; k++) r = fmaf(na[n * 10 + k], ae[k], r);
            out[n] = r;
        }
        __syncthreads();
        float hu = 0.f;
#pragma unroll
        for (int k = 0; k < 64; k++) hu = fmaf(hs[slot * 64 + k], Wup[k * 64 + c], hu);
        d_hup[n * 64 + c] = hu;
    } else {
        int i = (b - GEOM_BLKS - EMB_BLKS) * 128 + tid;
        if (i < 81920) {
            int t = i / 40960, r = i - t * 40960, n = r / 640, k = r - n * 640;
            float v = (k < 576) ? Wmix[t * 36864 + k * 64 + n]
                                : Wself[t * 4096 + (k - 576) * 64 + n];
            d_BT[t][r] = __float2half(v);
        } else if (i < 86016) {
            int q = i - 81920;
            int o = q >> 6, ii = q & 63;
            d_WupT[q] = __float2half(Wup[4096 + ii * 64 + o]);
        }
    }
}

// ---------------- single-kernel scan (1 block, 10 coalesced rounds) ----------------
__global__ __launch_bounds__(1024) void k_scan() {
    __shared__ int ws[32];
    __shared__ int tot_s;
    int t = threadIdx.x, lane = t & 31, w = t >> 5;
    int run = 0;
    for (int rr = 0; rr < 10; rr++) {
        int idx = rr * 1024 + t;
        int v = 0;
        if (idx < NN) { v = d_count[idx]; d_count[idx] = 0; }
        int inc = v;
#pragma unroll
        for (int o = 1; o < 32; o <<= 1) {
            int u = __shfl_up_sync(0xffffffffu, inc, o);
            if (lane >= o) inc += u;
        }
        if (lane == 31) ws[w] = inc;
        __syncthreads();
        if (w == 0) {
            int x = ws[lane];
            int xi = x;
#pragma unroll
            for (int o = 1; o < 32; o <<= 1) {
                int u = __shfl_up_sync(0xffffffffu, xi, o);
                if (lane >= o) xi += u;
            }
            ws[lane] = xi - x;
            if (lane == 31) tot_s = xi;
        }
        __syncthreads();
        int excl = run + ws[w] + inc - v;
        if (idx < NN) { d_offs[idx] = excl; d_cursor[idx] = excl; }
        run += tot_s;
        __syncthreads();
    }
    if (t == 0) d_offs[NN] = run;
}

// ---------------- fused scatter + heavy geometry at slot ----------------
__global__ __launch_bounds__(256) void k_scatgeo(const int* __restrict__ ei,
                                                 const float* __restrict__ Wr1) {
    __shared__ float Ws[256];
    Ws[threadIdx.x] = Wr1[threadIdx.x];
    __syncthreads();
    int e = blockIdx.x * 256 + threadIdx.x;
    if (e >= EE || !d_act[e]) return;
    int rv = ei[EE + e];
    int p = atomicAdd(&d_cursor[rv], 1);
    d_ssnd[p] = ei[e];

    float4 v = d_vec[e];
    float r = v.w;
    float inv = __fdividef(1.0f, r);
    float ux = v.x * inv, uy = v.y * inv, uz = v.z * inv;
    const float s3 = 1.7320508075688772f, s5 = 2.2360679774997896f, s15 = 3.872983346207417f;
    float4 fA = make_float4(1.0f, s3 * ux, s3 * uy, s3 * uz);
    float4 fB = make_float4(s15 * ux * uy, s15 * uy * uz,
                            0.5f * s5 * (3.0f * uz * uz - 1.0f), s15 * ux * uz);
    float4 fC = make_float4(0.5f * s15 * (ux * ux - uy * uy), 0.f, 0.f, 0.f);
    float4* shp = (float4*)&d_sh12[(long)p * 12];
    shp[0] = fA; shp[1] = fB; shp[2] = fC;

    float xx = r * (1.0f / RMAXF);
    float th = 3.14159265358979323846f * xx;
    float s1, c1;
    __sincosf(th, &s1, &c1);
    float x2 = xx * xx;
    float x6 = x2 * x2 * x2;
    float fc = 1.0f + x6 * (-28.0f + xx * (48.0f - 21.0f * xx));
    float pref = 0.6324555320336759f * inv * fc;
    float ef[8];
    float sp = 0.0f, sc = s1, c2 = 2.0f * c1;
#pragma unroll
    for (int n = 0; n < 8; n++) {
        ef[n] = pref * sc;
        float nx = c2 * sc - sp;
        sp = sc; sc = nx;
    }
#pragma unroll
    for (int t = 0; t < 2; t++) {
        float a[16];
#pragma unroll
        for (int m = 0; m < 16; m++) {
            float acc = 0.f;
#pragma unroll
            for (int n = 0; n < 8; n++) acc = fmaf(ef[n], Ws[t * 128 + n * 16 + m], acc);
            a[m] = __fdividef(acc, 1.0f + __expf(-acc));
        }
        float4* zp = (float4*)&d_z[t][(long)p * 16];
#pragma unroll
        for (int q = 0; q < 4; q++)
            zp[q] = make_float4(a[q * 4], a[q * 4 + 1], a[q * 4 + 2], a[q * 4 + 3]);
    }
}

// ---------------- agg: scalar, slot-indexed, half output ----------------
template<int SOFF, int SCNT>
__device__ __forceinline__ void agg_body(int c, int n0, int n1,
                                         const float* __restrict__ z,
                                         const float* __restrict__ Wr2) {
    float W[16][SCNT];
#pragma unroll
    for (int m = 0; m < 16; m++)
#pragma unroll
        for (int j = 0; j < SCNT; j++) W[m][j] = Wr2[m * 576 + c * 9 + SOFF + j];
    for (int n = n0; n < n1; n++) {
        float acc[SCNT];
#pragma unroll
        for (int j = 0; j < SCNT; j++) acc[j] = 0.f;
        int b = d_offs[n], e1 = d_offs[n + 1];
        for (int i = b; i < e1; i++) {
            float hv = __ldg(&d_hup[d_ssnd[i] * CC + c]);
            const float4* z4 = (const float4*)&z[(long)i * 16];
            float4 za = z4[0], zb = z4[1], zc = z4[2], zd = z4[3];
            float zz[16] = {za.x, za.y, za.z, za.w, zb.x, zb.y, zb.z, zb.w,
                            zc.x, zc.y, zc.z, zc.w, zd.x, zd.y, zd.z, zd.w};
            float shv[SCNT];
            if (SOFF == 0) {
                float4 sA = *(const float4*)&d_sh12[(long)i * 12];
                shv[0] = sA.x; shv[1] = sA.y; shv[2] = sA.z; shv[3] = sA.w;
                shv[4] = d_sh12[(long)i * 12 + 4];
            } else {
                float4 sB = *(const float4*)&d_sh12[(long)i * 12 + 4];
                shv[0] = sB.y; shv[1] = sB.z; shv[2] = sB.w;
                shv[3] = d_sh12[(long)i * 12 + 8];
            }
            float ws[SCNT];
#pragma unroll
            for (int j = 0; j < SCNT; j++) ws[j] = 0.f;
#pragma unroll
            for (int m = 0; m < 16; m++)
#pragma unroll
                for (int j = 0; j < SCNT; j++) ws[j] = fmaf(zz[m], W[m][j], ws[j]);
#pragma unroll
            for (int j = 0; j < SCNT; j++) acc[j] = fmaf(hv * shv[j], ws[j], acc[j]);
        }
#pragma unroll
        for (int j = 0; j < SCNT; j++)
            d_aggh[(long)n * 576 + c * 9 + SOFF + j] = __float2half(acc[j] * (1.0f / 32.0f));
    }
}

__global__ __launch_bounds__(128) void k_agg(int t, const float* __restrict__ Wr2) {
    int c = threadIdx.x & 63;
    int half_ = threadIdx.x >> 6;
    int n0 = blockIdx.x * NPB;
    int n1 = n0 + NPB; if (n1 > NN) n1 = NN;
    const float* z = d_z[t];
    if (half_ == 0) agg_body<0, 5>(c, n0, n1, z, Wr2);
    else            agg_body<5, 4>(c, n0, n1, z, Wr2);
}

// ---------------- update: fp16 MMA GEMM + fused epilogues ----------------
__global__ __launch_bounds__(128) void k_update(int t, const float* __restrict__ wread,
                                                const float* __restrict__ Wmlp1,
                                                const float* __restrict__ wmlp2,
                                                float* __restrict__ out) {
    __shared__ __half As[64][16];
    __shared__ __half BsT[64][16];
    __shared__ __half hS[64][72];
    __shared__ __half WuS[64 * 64];
    int tid = threadIdx.x, lane = tid & 31, w = tid >> 5;
    int m0 = blockIdx.x * 64;
    float C[8][4];
#pragma unroll
    for (int j = 0; j < 8; j++)
#pragma unroll
        for (int i = 0; i < 4; i++) C[j][i] = 0.f;

    int r = tid >> 1, hf = tid & 1;
    int node = m0 + r;
    int arf = 16 * w + (lane >> 2), akf = (lane & 3) * 2;

    for (int step = 0; step < 40; step++) {
        int k0 = step * 16;
        uint4 av = make_uint4(0, 0, 0, 0);
        if (node < NN) {
            const uint4* ap = (k0 < 576) ? (const uint4*)&d_aggh[(long)node * 576 + k0]
                                         : (const uint4*)&d_hh[node * 64 + (k0 - 576)];
            av = ap[hf];
        }
        uint4 bv = *((const uint4*)&d_BT[t][r * 640 + k0] + hf);
        __syncthreads();
        *(uint4*)&As[r][hf * 8] = av;
        *(uint4*)&BsT[r][hf * 8] = bv;
        __syncthreads();
        unsigned A0 = *(const unsigned*)&As[arf][akf];
        unsigned A1 = *(const unsigned*)&As[arf + 8][akf];
        unsigned A2 = *(const unsigned*)&As[arf][akf + 8];
        unsigned A3 = *(const unsigned*)&As[arf + 8][akf + 8];
#pragma unroll
        for (int j = 0; j < 8; j++) {
            int bn = j * 8 + (lane >> 2);
            unsigned B0 = *(const unsigned*)&BsT[bn][akf];
            unsigned B1 = *(const unsigned*)&BsT[bn][akf + 8];
            mma16816(C[j][0], C[j][1], C[j][2], C[j][3], A0, A1, A2, A3, B0, B1);
        }
    }
    __syncthreads();
    {
        int ac = 2 * (lane & 3);
#pragma unroll
        for (int j = 0; j < 8; j++) {
            *(__half2*)&hS[arf][j * 8 + ac]     = __floats2half2_rn(C[j][0], C[j][1]);
            *(__half2*)&hS[arf + 8][j * 8 + ac] = __floats2half2_rn(C[j][2], C[j][3]);
        }
    }
    __syncthreads();

    if (t == 0) {
        for (int i = tid; i < 64 * 32; i += 128) {
            int rr = i >> 5, cc2 = i & 31;
            if (m0 + rr < NN)
                ((__half2*)&d_hh[(m0 + rr) * 64])[cc2] = *(__half2*)&hS[rr][cc2 * 2];
        }
        if (tid < 64 && m0 + tid < NN) {
            float acc = 0.f;
#pragma unroll
            for (int k2 = 0; k2 < 64; k2++)
                acc = fmaf(__half2float(hS[tid][k2]), wread[k2], acc);
            out[NN + m0 + tid] = acc;
        }
        {
            const uint4* src = (const uint4*)d_WupT;
            uint4* dst = (uint4*)WuS;
#pragma unroll
            for (int i = 0; i < 4; i++) dst[tid + i * 128] = src[tid + i * 128];
        }
        __syncthreads();
        float H[8][4];
#pragma unroll
        for (int j = 0; j < 8; j++)
#pragma unroll
            for (int i = 0; i < 4; i++) H[j][i] = 0.f;
#pragma unroll
        for (int s = 0; s < 4; s++) {
            int k0 = s * 16;
            unsigned A0 = *(const unsigned*)&hS[arf][k0 + akf];
            unsigned A1 = *(const unsigned*)&hS[arf + 8][k0 + akf];
            unsigned A2 = *(const unsigned*)&hS[arf][k0 + akf + 8];
            unsigned A3 = *(const unsigned*)&hS[arf + 8][k0 + akf + 8];
#pragma unroll
            for (int j = 0; j < 8; j++) {
                int bn = j * 8 + (lane >> 2);
                unsigned B0 = *(const unsigned*)&WuS[bn * 64 + k0 + akf];
                unsigned B1 = *(const unsigned*)&WuS[bn * 64 + k0 + akf + 8];
                mma16816(H[j][0], H[j][1], H[j][2], H[j][3], A0, A1, A2, A3, B0, B1);
            }
        }
        int ac = 2 * (lane & 3);
#pragma unroll
        for (int j = 0; j < 8; j++) {
            int col = j * 8 + ac;
            if (m0 + arf < NN) {
                d_hup[(m0 + arf) * 64 + col] = H[j][0];
                d_hup[(m0 + arf) * 64 + col + 1] = H[j][1];
            }
            if (m0 + arf + 8 < NN) {
                d_hup[(m0 + arf + 8) * 64 + col] = H[j][2];
                d_hup[(m0 + arf + 8) * 64 + col + 1] = H[j][3];
            }
        }
    } else {
        int nd = tid >> 1, hf2 = tid & 1;
        float y[8];
#pragma unroll
        for (int o = 0; o < 8; o++) y[o] = 0.f;
        for (int k2 = 0; k2 < 64; k2++) {
            float hv = __half2float(hS[nd][k2]);
#pragma unroll
            for (int o = 0; o < 8; o++)
                y[o] = fmaf(hv, Wmlp1[k2 * 16 + hf2 * 8 + o], y[o]);
        }
        float acc = 0.f;
#pragma unroll
        for (int o = 0; o < 8; o++) {
            float s2 = __fdividef(y[o], 1.0f + __expf(-y[o]));
            acc = fmaf(s2, wmlp2[hf2 * 8 + o], acc);
        }
        acc += __shfl_xor_sync(0xffffffffu, acc, 1);
        if (hf2 == 0 && m0 + nd < NN) out[2 * NN + m0 + nd] = acc;
    }
}

// ---------------- host launch ----------------
extern "C" void kernel_launch(void* const* d_in, const int* in_sizes, int n_in,
                              void* d_out, int out_size) {
    const float *positions = nullptr, *node_attrs = nullptr, *shifts = nullptr;
    const float *atomic_energies = nullptr, *W_embed = nullptr, *W_up = nullptr;
    const float *W_r1 = nullptr, *W_r2 = nullptr, *W_mix = nullptr, *W_self = nullptr;
    const float *w_read = nullptr, *W_mlp1 = nullptr, *w_mlp2 = nullptr;
    const int* edge_index = nullptr;
    for (int i = 0; i < n_in; i++) {
        switch (in_sizes[i]) {
            case 30000:  positions = (const float*)d_in[i]; break;
            case 100000: node_attrs = (const float*)d_in[i]; break;
            case 480000: shifts = (const float*)d_in[i]; break;
            case 320000: edge_index = (const int*)d_in[i]; break;
            case 10:     atomic_energies = (const float*)d_in[i]; break;
            case 640:    W_embed = (const float*)d_in[i]; break;
            case 8192:   if (!W_up) W_up = (const float*)d_in[i];
                         else W_self = (const float*)d_in[i]; break;
            case 256:    W_r1 = (const float*)d_in[i]; break;
            case 18432:  W_r2 = (const float*)d_in[i]; break;
            case 73728:  W_mix = (const float*)d_in[i]; break;
            case 64:     w_read = (const float*)d_in[i]; break;
            case 1024:   W_mlp1 = (const float*)d_in[i]; break;
            case 16:     w_mlp2 = (const float*)d_in[i]; break;
            default: break;
        }
    }
    float* out = (float*)d_out;
    (void)out_size;

    k_setup<<<SETUP_BLKS, 128>>>(positions, shifts, edge_index, node_attrs, W_embed,
                                 atomic_energies, W_up, W_mix, W_self, out);
    k_scan<<<1, 1024>>>();
    k_scatgeo<<<GEOM_BLKS, 256>>>(edge_index, W_r1);

    for (int t = 0; t < 2; t++) {
        k_agg<<<(NN + NPB - 1) / NPB, 128>>>(t, W_r2 + t * 16 * 576);
        k_update<<<(NN + 63) / 64, 128>>>(t, w_read, W_mlp1, w_mlp2, out);
    }
}

// round 7
// speedup vs baseline: 3.0658x; 1.2003x over previous
#include <cuda_runtime.h>
#include <cuda_fp16.h>
#include <math.h>

#define NN 10000
#define EE 160000
#define CC 64
#define RMAXF 5.0f
#define NPB 8
#define CHK 32

#define GEOM_BLKS 625
#define EMB_BLKS  5000
#define PREP_BLKS 672
#define SETUP_BLKS (GEOM_BLKS + EMB_BLKS + PREP_BLKS)

// ---------------- device scratch ----------------
__device__ float4 d_vec[EE];           // (vx,vy,vz,r) for active edges
__device__ float d_sh12[EE * 12];      // slot-indexed sh (9 used, pad 12)
__device__ float d_z[2][EE * 16];      // slot-indexed silu(radial@W_r1)
__device__ unsigned char d_act[EE];
__device__ int   d_count[NN];          // zero-init; self-restored by k_scan
__device__ int   d_offs[NN + 1];
__device__ int   d_cursor[NN];
__device__ int   d_ssnd[EE];           // sender id per sorted slot
__device__ float d_hup[NN * CC];
__device__ __half d_hh[NN * CC];
__device__ __half d_aggh[NN * 576];
__device__ __half d_BT[2][64 * 640];   // [n][k] for update GEMM
__device__ __half d_WupT[64 * 64];     // W_up[1] transposed [o][i]

__device__ __forceinline__ void mma16816(float& c0, float& c1, float& c2, float& c3,
                                         unsigned a0, unsigned a1, unsigned a2, unsigned a3,
                                         unsigned b0, unsigned b1) {
    asm volatile(
        "mma.sync.aligned.m16n8k16.row.col.f32.f16.f16.f32 "
        "{%0,%1,%2,%3},{%4,%5,%6,%7},{%8,%9},{%0,%1,%2,%3};\n"
        : "+f"(c0), "+f"(c1), "+f"(c2), "+f"(c3)
        : "r"(a0), "r"(a1), "r"(a2), "r"(a3), "r"(b0), "r"(b1));
}

// ---------------- fused setup: geom1 | embed | weight prep ----------------
__device__ __forceinline__ void geom1_edge(int e, const float* __restrict__ pos,
                                           const float* __restrict__ shifts,
                                           const int* __restrict__ ei) {
    int s  = ei[e];
    int rv = ei[EE + e];
    float vx = pos[rv * 3 + 0] - pos[s * 3 + 0] + shifts[e * 3 + 0];
    float vy = pos[rv * 3 + 1] - pos[s * 3 + 1] + shifts[e * 3 + 1];
    float vz = pos[rv * 3 + 2] - pos[s * 3 + 2] + shifts[e * 3 + 2];
    float r = sqrtf(vx * vx + vy * vy + vz * vz) + 1e-9f;
    bool act = (r < RMAXF);
    d_act[e] = act ? 1 : 0;
    if (!act) return;
    atomicAdd(&d_count[rv], 1);
    d_vec[e] = make_float4(vx, vy, vz, r);
}

__global__ __launch_bounds__(128) void k_setup(const float* __restrict__ pos,
        const float* __restrict__ shifts, const int* __restrict__ ei,
        const float* __restrict__ na, const float* __restrict__ We,
        const float* __restrict__ ae, const float* __restrict__ Wup,
        const float* __restrict__ Wmix, const float* __restrict__ Wself,
        float* __restrict__ out) {
    int b = blockIdx.x, tid = threadIdx.x;
    if (b < GEOM_BLKS) {
        int e0 = b * 256 + tid;
        geom1_edge(e0, pos, shifts, ei);
        geom1_edge(e0 + 128, pos, shifts, ei);
    } else if (b < GEOM_BLKS + EMB_BLKS) {
        __shared__ float hs[128];
        int slot = tid >> 6, c = tid & 63;
        int n = (b - GEOM_BLKS) * 2 + slot;
        float acc = 0.f;
#pragma unroll
        for (int k = 0; k < 10; k++) acc = fmaf(na[n * 10 + k], We[k * 64 + c], acc);
        hs[tid] = acc;
        d_hh[n * 64 + c] = __float2half(acc);
        if (c == 0) {
            float r = 0.f;
#pragma unroll
            for (int k = 0; k < 10; k++) r = fmaf(na[n * 10 + k], ae[k], r);
            out[n] = r;
        }
        __syncthreads();
        float hu = 0.f;
#pragma unroll
        for (int k = 0; k < 64; k++) hu = fmaf(hs[slot * 64 + k], Wup[k * 64 + c], hu);
        d_hup[n * 64 + c] = hu;
    } else {
        int i = (b - GEOM_BLKS - EMB_BLKS) * 128 + tid;
        if (i < 81920) {
            int t = i / 40960, r = i - t * 40960, n = r / 640, k = r - n * 640;
            float v = (k < 576) ? Wmix[t * 36864 + k * 64 + n]
                                : Wself[t * 4096 + (k - 576) * 64 + n];
            d_BT[t][r] = __float2half(v);
        } else if (i < 86016) {
            int q = i - 81920;
            int o = q >> 6, ii = q & 63;
            d_WupT[q] = __float2half(Wup[4096 + ii * 64 + o]);
        }
    }
}

// ---------------- single-kernel scan ----------------
__global__ __launch_bounds__(1024) void k_scan() {
    __shared__ int ws[32];
    __shared__ int tot_s;
    int t = threadIdx.x, lane = t & 31, w = t >> 5;
    int run = 0;
    for (int rr = 0; rr < 10; rr++) {
        int idx = rr * 1024 + t;
        int v = 0;
        if (idx < NN) { v = d_count[idx]; d_count[idx] = 0; }
        int inc = v;
#pragma unroll
        for (int o = 1; o < 32; o <<= 1) {
            int u = __shfl_up_sync(0xffffffffu, inc, o);
            if (lane >= o) inc += u;
        }
        if (lane == 31) ws[w] = inc;
        __syncthreads();
        if (w == 0) {
            int x = ws[lane];
            int xi = x;
#pragma unroll
            for (int o = 1; o < 32; o <<= 1) {
                int u = __shfl_up_sync(0xffffffffu, xi, o);
                if (lane >= o) xi += u;
            }
            ws[lane] = xi - x;
            if (lane == 31) tot_s = xi;
        }
        __syncthreads();
        int excl = run + ws[w] + inc - v;
        if (idx < NN) { d_offs[idx] = excl; d_cursor[idx] = excl; }
        run += tot_s;
        __syncthreads();
    }
    if (t == 0) d_offs[NN] = run;
}

// ---------------- fused scatter + heavy geometry at slot ----------------
__global__ __launch_bounds__(256) void k_scatgeo(const int* __restrict__ ei,
                                                 const float* __restrict__ Wr1) {
    __shared__ float Ws[256];
    Ws[threadIdx.x] = Wr1[threadIdx.x];
    __syncthreads();
    int e = blockIdx.x * 256 + threadIdx.x;
    if (e >= EE || !d_act[e]) return;
    int rv = ei[EE + e];
    int p = atomicAdd(&d_cursor[rv], 1);
    d_ssnd[p] = ei[e];

    float4 v = d_vec[e];
    float r = v.w;
    float inv = __fdividef(1.0f, r);
    float ux = v.x * inv, uy = v.y * inv, uz = v.z * inv;
    const float s3 = 1.7320508075688772f, s5 = 2.2360679774997896f, s15 = 3.872983346207417f;
    float4 fA = make_float4(1.0f, s3 * ux, s3 * uy, s3 * uz);
    float4 fB = make_float4(s15 * ux * uy, s15 * uy * uz,
                            0.5f * s5 * (3.0f * uz * uz - 1.0f), s15 * ux * uz);
    float4 fC = make_float4(0.5f * s15 * (ux * ux - uy * uy), 0.f, 0.f, 0.f);
    float4* shp = (float4*)&d_sh12[(long)p * 12];
    shp[0] = fA; shp[1] = fB; shp[2] = fC;

    float xx = r * (1.0f / RMAXF);
    float th = 3.14159265358979323846f * xx;
    float s1, c1;
    __sincosf(th, &s1, &c1);
    float x2 = xx * xx;
    float x6 = x2 * x2 * x2;
    float fc = 1.0f + x6 * (-28.0f + xx * (48.0f - 21.0f * xx));
    float pref = 0.6324555320336759f * inv * fc;
    float ef[8];
    float sp = 0.0f, sc = s1, c2 = 2.0f * c1;
#pragma unroll
    for (int n = 0; n < 8; n++) {
        ef[n] = pref * sc;
        float nx = c2 * sc - sp;
        sp = sc; sc = nx;
    }
#pragma unroll
    for (int t = 0; t < 2; t++) {
        float a[16];
#pragma unroll
        for (int m = 0; m < 16; m++) {
            float acc = 0.f;
#pragma unroll
            for (int n = 0; n < 8; n++) acc = fmaf(ef[n], Ws[t * 128 + n * 16 + m], acc);
            a[m] = __fdividef(acc, 1.0f + __expf(-acc));
        }
        float4* zp = (float4*)&d_z[t][(long)p * 16];
#pragma unroll
        for (int q = 0; q < 4; q++)
            zp[q] = make_float4(a[q * 4], a[q * 4 + 1], a[q * 4 + 2], a[q * 4 + 3]);
    }
}

// ---------------- agg: smem-staged chunks, boundary-walk, half output ----------------
template<int SOFF, int SCNT>
__device__ __forceinline__ void agg_core(int tid, int c, int n0,
                                         const float* __restrict__ z,
                                         const float* __restrict__ Wr2,
                                         float (*zS)[16], float (*shS)[12],
                                         int* sndS, const int* offsS) {
    float W[16][SCNT];
#pragma unroll
    for (int m = 0; m < 16; m++)
#pragma unroll
        for (int j = 0; j < SCNT; j++) W[m][j] = Wr2[m * 576 + c * 9 + SOFF + j];

    int iBeg = offsS[0], iEnd = offsS[8];
    int kn = 0;
    int nextb = offsS[1];
    float acc[SCNT];
#pragma unroll
    for (int j = 0; j < SCNT; j++) acc[j] = 0.f;

    for (int base = iBeg; base < iEnd; base += CHK) {
        int cnt = min(CHK, iEnd - base);
        __syncthreads();
        {   // stage z: 128 threads x 1 float4 = 32 edges x 16 floats
            int e = tid >> 2, p = tid & 3;
            *(float4*)&zS[e][p * 4] = *(const float4*)&z[(long)(base + e) * 16 + p * 4];
        }
        if (tid < 96) {   // stage sh: 32 edges x 12 floats
            int e = tid / 3, p = tid - e * 3;
            *(float4*)&shS[e][p * 4] = *(const float4*)&d_sh12[(long)(base + e) * 12 + p * 4];
        }
        if (tid < CHK) sndS[tid] = d_ssnd[base + tid];
        __syncthreads();

        for (int e = 0; e < cnt; e++) {
            int i = base + e;
            while (i >= nextb) {   // uniform across block
#pragma unroll
                for (int j = 0; j < SCNT; j++)
                    d_aggh[(long)(n0 + kn) * 576 + c * 9 + SOFF + j] =
                        __float2half(acc[j] * (1.0f / 32.0f));
#pragma unroll
                for (int j = 0; j < SCNT; j++) acc[j] = 0.f;
                kn++;
                nextb = (kn < 8) ? offsS[kn + 1] : 0x7fffffff;
            }
            float hv = d_hup[sndS[e] * CC + c];
            float ws[SCNT];
#pragma unroll
            for (int j = 0; j < SCNT; j++) ws[j] = 0.f;
#pragma unroll
            for (int m = 0; m < 16; m++) {
                float zm = zS[e][m];
#pragma unroll
                for (int j = 0; j < SCNT; j++) ws[j] = fmaf(zm, W[m][j], ws[j]);
            }
#pragma unroll
            for (int j = 0; j < SCNT; j++)
                acc[j] = fmaf(hv * shS[e][SOFF + j], ws[j], acc[j]);
        }
    }
    // flush remaining nodes (also handles all-empty blocks)
    while (kn < 8) {
#pragma unroll
        for (int j = 0; j < SCNT; j++)
            d_aggh[(long)(n0 + kn) * 576 + c * 9 + SOFF + j] =
                __float2half(acc[j] * (1.0f / 32.0f));
#pragma unroll
        for (int j = 0; j < SCNT; j++) acc[j] = 0.f;
        kn++;
    }
}

__global__ __launch_bounds__(128) void k_agg(int t, const float* __restrict__ Wr2) {
    __shared__ float zS[CHK][16];
    __shared__ float shS[CHK][12];
    __shared__ int sndS[CHK];
    __shared__ int offsS[9];
    int tid = threadIdx.x;
    int c = tid & 63;
    int half_ = tid >> 6;
    int n0 = blockIdx.x * NPB;
    if (tid < 9) offsS[tid] = d_offs[n0 + tid];
    __syncthreads();
    const float* z = d_z[t];
    if (half_ == 0) agg_core<0, 5>(tid, c, n0, z, Wr2, zS, shS, sndS, offsS);
    else            agg_core<5, 4>(tid, c, n0, z, Wr2, zS, shS, sndS, offsS);
}

// ---------------- update: fp16 MMA GEMM + fused epilogues ----------------
__global__ __launch_bounds__(128) void k_update(int t, const float* __restrict__ wread,
                                                const float* __restrict__ Wmlp1,
                                                const float* __restrict__ wmlp2,
                                                float* __restrict__ out) {
    __shared__ __half As[64][16];
    __shared__ __half BsT[64][16];
    __shared__ __half hS[64][72];
    __shared__ __half WuS[64 * 64];
    int tid = threadIdx.x, lane = tid & 31, w = tid >> 5;
    int m0 = blockIdx.x * 64;
    float C[8][4];
#pragma unroll
    for (int j = 0; j < 8; j++)
#pragma unroll
        for (int i = 0; i < 4; i++) C[j][i] = 0.f;

    int r = tid >> 1, hf = tid & 1;
    int node = m0 + r;
    int arf = 16 * w + (lane >> 2), akf = (lane & 3) * 2;

    for (int step = 0; step < 40; step++) {
        int k0 = step * 16;
        uint4 av = make_uint4(0, 0, 0, 0);
        if (node < NN) {
            const uint4* ap = (k0 < 576) ? (const uint4*)&d_aggh[(long)node * 576 + k0]
                                         : (const uint4*)&d_hh[node * 64 + (k0 - 576)];
            av = ap[hf];
        }
        uint4 bv = *((const uint4*)&d_BT[t][r * 640 + k0] + hf);
        __syncthreads();
        *(uint4*)&As[r][hf * 8] = av;
        *(uint4*)&BsT[r][hf * 8] = bv;
        __syncthreads();
        unsigned A0 = *(const unsigned*)&As[arf][akf];
        unsigned A1 = *(const unsigned*)&As[arf + 8][akf];
        unsigned A2 = *(const unsigned*)&As[arf][akf + 8];
        unsigned A3 = *(const unsigned*)&As[arf + 8][akf + 8];
#pragma unroll
        for (int j = 0; j < 8; j++) {
            int bn = j * 8 + (lane >> 2);
            unsigned B0 = *(const unsigned*)&BsT[bn][akf];
            unsigned B1 = *(const unsigned*)&BsT[bn][akf + 8];
            mma16816(C[j][0], C[j][1], C[j][2], C[j][3], A0, A1, A2, A3, B0, B1);
        }
    }
    __syncthreads();
    {
        int ac = 2 * (lane & 3);
#pragma unroll
        for (int j = 0; j < 8; j++) {
            *(__half2*)&hS[arf][j * 8 + ac]     = __floats2half2_rn(C[j][0], C[j][1]);
            *(__half2*)&hS[arf + 8][j * 8 + ac] = __floats2half2_rn(C[j][2], C[j][3]);
        }
    }
    __syncthreads();

    if (t == 0) {
        for (int i = tid; i < 64 * 32; i += 128) {
            int rr = i >> 5, cc2 = i & 31;
            if (m0 + rr < NN)
                ((__half2*)&d_hh[(m0 + rr) * 64])[cc2] = *(__half2*)&hS[rr][cc2 * 2];
        }
        if (tid < 64 && m0 + tid < NN) {
            float acc = 0.f;
#pragma unroll
            for (int k2 = 0; k2 < 64; k2++)
                acc = fmaf(__half2float(hS[tid][k2]), wread[k2], acc);
            out[NN + m0 + tid] = acc;
        }
        {
            const uint4* src = (const uint4*)d_WupT;
            uint4* dst = (uint4*)WuS;
#pragma unroll
            for (int i = 0; i < 4; i++) dst[tid + i * 128] = src[tid + i * 128];
        }
        __syncthreads();
        float H[8][4];
#pragma unroll
        for (int j = 0; j < 8; j++)
#pragma unroll
            for (int i = 0; i < 4; i++) H[j][i] = 0.f;
#pragma unroll
        for (int s = 0; s < 4; s++) {
            int k0 = s * 16;
            unsigned A0 = *(const unsigned*)&hS[arf][k0 + akf];
            unsigned A1 = *(const unsigned*)&hS[arf + 8][k0 + akf];
            unsigned A2 = *(const unsigned*)&hS[arf][k0 + akf + 8];
            unsigned A3 = *(const unsigned*)&hS[arf + 8][k0 + akf + 8];
#pragma unroll
            for (int j = 0; j < 8; j++) {
                int bn = j * 8 + (lane >> 2);
                unsigned B0 = *(const unsigned*)&WuS[bn * 64 + k0 + akf];
                unsigned B1 = *(const unsigned*)&WuS[bn * 64 + k0 + akf + 8];
                mma16816(H[j][0], H[j][1], H[j][2], H[j][3], A0, A1, A2, A3, B0, B1);
            }
        }
        int ac = 2 * (lane & 3);
#pragma unroll
        for (int j = 0; j < 8; j++) {
            int col = j * 8 + ac;
            if (m0 + arf < NN) {
                d_hup[(m0 + arf) * 64 + col] = H[j][0];
                d_hup[(m0 + arf) * 64 + col + 1] = H[j][1];
            }
            if (m0 + arf + 8 < NN) {
                d_hup[(m0 + arf + 8) * 64 + col] = H[j][2];
                d_hup[(m0 + arf + 8) * 64 + col + 1] = H[j][3];
            }
        }
    } else {
        int nd = tid >> 1, hf2 = tid & 1;
        float y[8];
#pragma unroll
        for (int o = 0; o < 8; o++) y[o] = 0.f;
        for (int k2 = 0; k2 < 64; k2++) {
            float hv = __half2float(hS[nd][k2]);
#pragma unroll
            for (int o = 0; o < 8; o++)
                y[o] = fmaf(hv, Wmlp1[k2 * 16 + hf2 * 8 + o], y[o]);
        }
        float acc = 0.f;
#pragma unroll
        for (int o = 0; o < 8; o++) {
            float s2 = __fdividef(y[o], 1.0f + __expf(-y[o]));
            acc = fmaf(s2, wmlp2[hf2 * 8 + o], acc);
        }
        acc += __shfl_xor_sync(0xffffffffu, acc, 1);
        if (hf2 == 0 && m0 + nd < NN) out[2 * NN + m0 + nd] = acc;
    }
}

// ---------------- host launch ----------------
extern "C" void kernel_launch(void* const* d_in, const int* in_sizes, int n_in,
                              void* d_out, int out_size) {
    const float *positions = nullptr, *node_attrs = nullptr, *shifts = nullptr;
    const float *atomic_energies = nullptr, *W_embed = nullptr, *W_up = nullptr;
    const float *W_r1 = nullptr, *W_r2 = nullptr, *W_mix = nullptr, *W_self = nullptr;
    const float *w_read = nullptr, *W_mlp1 = nullptr, *w_mlp2 = nullptr;
    const int* edge_index = nullptr;
    for (int i = 0; i < n_in; i++) {
        switch (in_sizes[i]) {
            case 30000:  positions = (const float*)d_in[i]; break;
            case 100000: node_attrs = (const float*)d_in[i]; break;
            case 480000: shifts = (const float*)d_in[i]; break;
            case 320000: edge_index = (const int*)d_in[i]; break;
            case 10:     atomic_energies = (const float*)d_in[i]; break;
            case 640:    W_embed = (const float*)d_in[i]; break;
            case 8192:   if (!W_up) W_up = (const float*)d_in[i];
                         else W_self = (const float*)d_in[i]; break;
            case 256:    W_r1 = (const float*)d_in[i]; break;
            case 18432:  W_r2 = (const float*)d_in[i]; break;
            case 73728:  W_mix = (const float*)d_in[i]; break;
            case 64:     w_read = (const float*)d_in[i]; break;
            case 1024:   W_mlp1 = (const float*)d_in[i]; break;
            case 16:     w_mlp2 = (const float*)d_in[i]; break;
            default: break;
        }
    }
    float* out = (float*)d_out;
    (void)out_size;

    k_setup<<<SETUP_BLKS, 128>>>(positions, shifts, edge_index, node_attrs, W_embed,
                                 atomic_energies, W_up, W_mix, W_self, out);
    k_scan<<<1, 1024>>>();
    k_scatgeo<<<GEOM_BLKS, 256>>>(edge_index, W_r1);

    for (int t = 0; t < 2; t++) {
        k_agg<<<(NN + NPB - 1) / NPB, 128>>>(t, W_r2 + t * 16 * 576);
        k_update<<<(NN + 63) / 64, 128>>>(t, w_read, W_mlp1, w_mlp2, out);
    }
}

// round 8
// speedup vs baseline: 3.8387x; 1.2521x over previous
#include <cuda_runtime.h>
#include <cuda_fp16.h>
#include <math.h>

#define NN 10000
#define EE 160000
#define CC 64
#define RMAXF 5.0f
#define NPB 8
#define TPW_PAD 584

#define GEOM_BLKS 625
#define EMB_BLKS  5000
#define PREP_BLKS 672
#define SETUP_BLKS (GEOM_BLKS + EMB_BLKS + PREP_BLKS)

// ---------------- device scratch ----------------
__device__ float4 d_vec[EE];
__device__ float d_sh12[EE * 12];      // slot-indexed sh (9 used, pad 12)
__device__ __half d_zh[2][EE * 16];    // slot-indexed silu(radial@W_r1), half
__device__ unsigned char d_act[EE];
__device__ int   d_count[NN];
__device__ int   d_offs[NN + 1];
__device__ int   d_cursor[NN];
__device__ int   d_ssnd[EE];
__device__ float d_hup[NN * CC];
__device__ __half d_hh[NN * CC];
__device__ __half d_aggh[NN * 576];
__device__ __half d_W2T[2][576 * 16];  // [cg][m] for agg MMA (B operand)
__device__ __half d_BT[2][64 * 640];   // [n][k] for update GEMM
__device__ __half d_WupT[64 * 64];

__device__ __forceinline__ void mma16816(float& c0, float& c1, float& c2, float& c3,
                                         unsigned a0, unsigned a1, unsigned a2, unsigned a3,
                                         unsigned b0, unsigned b1) {
    asm volatile(
        "mma.sync.aligned.m16n8k16.row.col.f32.f16.f16.f32 "
        "{%0,%1,%2,%3},{%4,%5,%6,%7},{%8,%9},{%0,%1,%2,%3};\n"
        : "+f"(c0), "+f"(c1), "+f"(c2), "+f"(c3)
        : "r"(a0), "r"(a1), "r"(a2), "r"(a3), "r"(b0), "r"(b1));
}

// ---------------- fused setup: geom1 | embed | weight prep ----------------
__device__ __forceinline__ void geom1_edge(int e, const float* __restrict__ pos,
                                           const float* __restrict__ shifts,
                                           const int* __restrict__ ei) {
    int s  = ei[e];
    int rv = ei[EE + e];
    float vx = pos[rv * 3 + 0] - pos[s * 3 + 0] + shifts[e * 3 + 0];
    float vy = pos[rv * 3 + 1] - pos[s * 3 + 1] + shifts[e * 3 + 1];
    float vz = pos[rv * 3 + 2] - pos[s * 3 + 2] + shifts[e * 3 + 2];
    float r = sqrtf(vx * vx + vy * vy + vz * vz) + 1e-9f;
    bool act = (r < RMAXF);
    d_act[e] = act ? 1 : 0;
    if (!act) return;
    atomicAdd(&d_count[rv], 1);
    d_vec[e] = make_float4(vx, vy, vz, r);
}

__global__ __launch_bounds__(128) void k_setup(const float* __restrict__ pos,
        const float* __restrict__ shifts, const int* __restrict__ ei,
        const float* __restrict__ na, const float* __restrict__ We,
        const float* __restrict__ ae, const float* __restrict__ Wup,
        const float* __restrict__ Wmix, const float* __restrict__ Wself,
        const float* __restrict__ Wr2, float* __restrict__ out) {
    int b = blockIdx.x, tid = threadIdx.x;
    if (b < GEOM_BLKS) {
        int e0 = b * 256 + tid;
        geom1_edge(e0, pos, shifts, ei);
        geom1_edge(e0 + 128, pos, shifts, ei);
    } else if (b < GEOM_BLKS + EMB_BLKS) {
        __shared__ float hs[128];
        int slot = tid >> 6, c = tid & 63;
        int n = (b - GEOM_BLKS) * 2 + slot;
        float acc = 0.f;
#pragma unroll
        for (int k = 0; k < 10; k++) acc = fmaf(na[n * 10 + k], We[k * 64 + c], acc);
        hs[tid] = acc;
        d_hh[n * 64 + c] = __float2half(acc);
        if (c == 0) {
            float r = 0.f;
#pragma unroll
            for (int k = 0; k < 10; k++) r = fmaf(na[n * 10 + k], ae[k], r);
            out[n] = r;
        }
        __syncthreads();
        float hu = 0.f;
#pragma unroll
        for (int k = 0; k < 64; k++) hu = fmaf(hs[slot * 64 + k], Wup[k * 64 + c], hu);
        d_hup[n * 64 + c] = hu;
    } else {
        int i = (b - GEOM_BLKS - EMB_BLKS) * 128 + tid;
        if (i < 81920) {
            int t = i / 40960, r = i - t * 40960, n = r / 640, k = r - n * 640;
            float v = (k < 576) ? Wmix[t * 36864 + k * 64 + n]
                                : Wself[t * 4096 + (k - 576) * 64 + n];
            d_BT[t][r] = __float2half(v);
        } else if (i < 86016) {
            int q = i - 81920;
            int o = q >> 6, ii = q & 63;
            d_WupT[q] = __float2half(Wup[4096 + ii * 64 + o]);
        }
        // W_r2 -> half, transposed to [cg][m]
        int j = i;
        if (j < 2 * 9216) {
            int t = j / 9216, r = j - t * 9216, cg = r >> 4, m = r & 15;
            d_W2T[t][r] = __float2half(Wr2[t * 9216 + m * 576 + cg]);
        }
    }
}

// ---------------- single-kernel scan ----------------
__global__ __launch_bounds__(1024) void k_scan() {
    __shared__ int ws[32];
    __shared__ int tot_s;
    int t = threadIdx.x, lane = t & 31, w = t >> 5;
    int run = 0;
    for (int rr = 0; rr < 10; rr++) {
        int idx = rr * 1024 + t;
        int v = 0;
        if (idx < NN) { v = d_count[idx]; d_count[idx] = 0; }
        int inc = v;
#pragma unroll
        for (int o = 1; o < 32; o <<= 1) {
            int u = __shfl_up_sync(0xffffffffu, inc, o);
            if (lane >= o) inc += u;
        }
        if (lane == 31) ws[w] = inc;
        __syncthreads();
        if (w == 0) {
            int x = ws[lane];
            int xi = x;
#pragma unroll
            for (int o = 1; o < 32; o <<= 1) {
                int u = __shfl_up_sync(0xffffffffu, xi, o);
                if (lane >= o) xi += u;
            }
            ws[lane] = xi - x;
            if (lane == 31) tot_s = xi;
        }
        __syncthreads();
        int excl = run + ws[w] + inc - v;
        if (idx < NN) { d_offs[idx] = excl; d_cursor[idx] = excl; }
        run += tot_s;
        __syncthreads();
    }
    if (t == 0) d_offs[NN] = run;
}

// ---------------- fused scatter + heavy geometry at slot ----------------
__global__ __launch_bounds__(256) void k_scatgeo(const int* __restrict__ ei,
                                                 const float* __restrict__ Wr1) {
    __shared__ float Ws[256];
    Ws[threadIdx.x] = Wr1[threadIdx.x];
    __syncthreads();
    int e = blockIdx.x * 256 + threadIdx.x;
    if (e >= EE || !d_act[e]) return;
    int rv = ei[EE + e];
    int p = atomicAdd(&d_cursor[rv], 1);
    d_ssnd[p] = ei[e];

    float4 v = d_vec[e];
    float r = v.w;
    float inv = __fdividef(1.0f, r);
    float ux = v.x * inv, uy = v.y * inv, uz = v.z * inv;
    const float s3 = 1.7320508075688772f, s5 = 2.2360679774997896f, s15 = 3.872983346207417f;
    float4 fA = make_float4(1.0f, s3 * ux, s3 * uy, s3 * uz);
    float4 fB = make_float4(s15 * ux * uy, s15 * uy * uz,
                            0.5f * s5 * (3.0f * uz * uz - 1.0f), s15 * ux * uz);
    float4 fC = make_float4(0.5f * s15 * (ux * ux - uy * uy), 0.f, 0.f, 0.f);
    float4* shp = (float4*)&d_sh12[(long)p * 12];
    shp[0] = fA; shp[1] = fB; shp[2] = fC;

    float xx = r * (1.0f / RMAXF);
    float th = 3.14159265358979323846f * xx;
    float s1, c1;
    __sincosf(th, &s1, &c1);
    float x2 = xx * xx;
    float x6 = x2 * x2 * x2;
    float fc = 1.0f + x6 * (-28.0f + xx * (48.0f - 21.0f * xx));
    float pref = 0.6324555320336759f * inv * fc;
    float ef[8];
    float sp = 0.0f, sc = s1, c2 = 2.0f * c1;
#pragma unroll
    for (int n = 0; n < 8; n++) {
        ef[n] = pref * sc;
        float nx = c2 * sc - sp;
        sp = sc; sc = nx;
    }
#pragma unroll
    for (int t = 0; t < 2; t++) {
        float a[16];
#pragma unroll
        for (int m = 0; m < 16; m++) {
            float acc = 0.f;
#pragma unroll
            for (int n = 0; n < 8; n++) acc = fmaf(ef[n], Ws[t * 128 + n * 16 + m], acc);
            a[m] = __fdividef(acc, 1.0f + __expf(-acc));
        }
        __half2 hz[8];
#pragma unroll
        for (int q = 0; q < 8; q++) hz[q] = __floats2half2_rn(a[2 * q], a[2 * q + 1]);
        uint4* zp = (uint4*)&d_zh[t][(long)p * 16];
        zp[0] = *(uint4*)&hz[0];
        zp[1] = *(uint4*)&hz[4];
    }
}

// ---------------- agg: MMA tp_w into smem + scalar epilogue ----------------
template<int SOFF, int SCNT>
__device__ __forceinline__ void agg_core(int tid, int c, int n0,
        const __half* __restrict__ zg,
        const unsigned* Bf0, const unsigned* Bf1,
        float (*tpwS)[TPW_PAD], float (*hupS)[64], __half (*zS)[16],
        float (*shS)[12], int* sndS, const int* offsS) {
    int lane = tid & 31, w = tid >> 5;
    int ar = lane >> 2, ak = (lane & 3) * 2;
    int iBeg = offsS[0], iEnd = offsS[8];
    int kn = 0, nextb = offsS[1];
    float acc[SCNT];
#pragma unroll
    for (int j = 0; j < SCNT; j++) acc[j] = 0.f;

    for (int base = iBeg; base < iEnd; base += 16) {
        int cnt = min(16, iEnd - base);
        __syncthreads();                       // previous epilogue done
        if (tid < 32) {                        // z: 16 edges x 16 half
            int e = tid >> 1, p = tid & 1;
            *(uint4*)&zS[e][p * 8] = *(const uint4*)&zg[(long)(base + e) * 16 + p * 8];
        }
        if (tid < 48) {                        // sh: 16 edges x 12 f
            int e = tid / 3, p = tid - e * 3;
            *(float4*)&shS[e][p * 4] = *(const float4*)&d_sh12[(long)(base + e) * 12 + p * 4];
        }
        if (tid < 16) sndS[tid] = d_ssnd[base + tid];
        __syncthreads();
        {                                      // hup: 16 edges x 64 f
            int e = tid >> 3, cq = tid & 7;
            int sn = sndS[e];
            const float4* hp = (const float4*)&d_hup[sn * 64 + cq * 8];
            *(float4*)&hupS[e][cq * 8] = hp[0];
            *(float4*)&hupS[e][cq * 8 + 4] = hp[1];
        }
        unsigned A0 = *(const unsigned*)&zS[ar][ak];
        unsigned A1 = *(const unsigned*)&zS[ar + 8][ak];
        unsigned A2 = *(const unsigned*)&zS[ar][ak + 8];
        unsigned A3 = *(const unsigned*)&zS[ar + 8][ak + 8];
#pragma unroll
        for (int q = 0; q < 18; q++) {
            int cb = (w * 18 + q) * 8;
            float c0 = 0.f, c1 = 0.f, c2 = 0.f, c3 = 0.f;
            mma16816(c0, c1, c2, c3, A0, A1, A2, A3, Bf0[q], Bf1[q]);
            int cg0 = cb + 2 * (lane & 3);
            *(float2*)&tpwS[ar][cg0]     = make_float2(c0, c1);
            *(float2*)&tpwS[ar + 8][cg0] = make_float2(c2, c3);
        }
        __syncthreads();

        for (int e = 0; e < cnt; e++) {
            int i = base + e;
            while (i >= nextb) {               // uniform across block
#pragma unroll
                for (int j = 0; j < SCNT; j++)
                    d_aggh[(long)(n0 + kn) * 576 + c * 9 + SOFF + j] =
                        __float2half(acc[j] * (1.0f / 32.0f));
#pragma unroll
                for (int j = 0; j < SCNT; j++) acc[j] = 0.f;
                kn++;
                nextb = (kn < 8) ? offsS[kn + 1] : 0x7fffffff;
            }
            float hv = hupS[e][c];
#pragma unroll
            for (int j = 0; j < SCNT; j++)
                acc[j] = fmaf(hv * shS[e][SOFF + j], tpwS[e][c * 9 + SOFF + j], acc[j]);
        }
    }
    while (kn < 8) {
#pragma unroll
        for (int j = 0; j < SCNT; j++)
            d_aggh[(long)(n0 + kn) * 576 + c * 9 + SOFF + j] =
                __float2half(acc[j] * (1.0f / 32.0f));
#pragma unroll
        for (int j = 0; j < SCNT; j++) acc[j] = 0.f;
        kn++;
    }
}

__global__ __launch_bounds__(128) void k_agg(int t) {
    __shared__ float tpwS[16][TPW_PAD];
    __shared__ float hupS[16][64];
    __shared__ __half zS[16][16];
    __shared__ float shS[16][12];
    __shared__ int sndS[16];
    __shared__ int offsS[9];
    int tid = threadIdx.x, lane = tid & 31, w = tid >> 5;
    int n0 = blockIdx.x * NPB;
    if (tid < 9) offsS[tid] = d_offs[n0 + tid];

    const __half* W2 = d_W2T[t];
    unsigned Bf0[18], Bf1[18];
    int ar = lane >> 2, ak = (lane & 3) * 2;
#pragma unroll
    for (int q = 0; q < 18; q++) {
        int cb = (w * 18 + q) * 8;
        Bf0[q] = *(const unsigned*)&W2[(cb + ar) * 16 + ak];
        Bf1[q] = *(const unsigned*)&W2[(cb + ar) * 16 + ak + 8];
    }
    __syncthreads();
    const __half* zg = d_zh[t];
    int c = tid & 63;
    if (tid < 64) agg_core<0, 5>(tid, c, n0, zg, Bf0, Bf1, tpwS, hupS, zS, shS, sndS, offsS);
    else          agg_core<5, 4>(tid, c, n0, zg, Bf0, Bf1, tpwS, hupS, zS, shS, sndS, offsS);
}

// ---------------- update: fp16 MMA GEMM + fused epilogues ----------------
__global__ __launch_bounds__(128) void k_update(int t, const float* __restrict__ wread,
                                                const float* __restrict__ Wmlp1,
                                                const float* __restrict__ wmlp2,
                                                float* __restrict__ out) {
    __shared__ __half As[64][16];
    __shared__ __half BsT[64][16];
    __shared__ __half hS[64][72];
    __shared__ __half WuS[64 * 64];
    int tid = threadIdx.x, lane = tid & 31, w = tid >> 5;
    int m0 = blockIdx.x * 64;
    float C[8][4];
#pragma unroll
    for (int j = 0; j < 8; j++)
#pragma unroll
        for (int i = 0; i < 4; i++) C[j][i] = 0.f;

    int r = tid >> 1, hf = tid & 1;
    int node = m0 + r;
    int arf = 16 * w + (lane >> 2), akf = (lane & 3) * 2;

    for (int step = 0; step < 40; step++) {
        int k0 = step * 16;
        uint4 av = make_uint4(0, 0, 0, 0);
        if (node < NN) {
            const uint4* ap = (k0 < 576) ? (const uint4*)&d_aggh[(long)node * 576 + k0]
                                         : (const uint4*)&d_hh[node * 64 + (k0 - 576)];
            av = ap[hf];
        }
        uint4 bv = *((const uint4*)&d_BT[t][r * 640 + k0] + hf);
        __syncthreads();
        *(uint4*)&As[r][hf * 8] = av;
        *(uint4*)&BsT[r][hf * 8] = bv;
        __syncthreads();
        unsigned A0 = *(const unsigned*)&As[arf][akf];
        unsigned A1 = *(const unsigned*)&As[arf + 8][akf];
        unsigned A2 = *(const unsigned*)&As[arf][akf + 8];
        unsigned A3 = *(const unsigned*)&As[arf + 8][akf + 8];
#pragma unroll
        for (int j = 0; j < 8; j++) {
            int bn = j * 8 + (lane >> 2);
            unsigned B0 = *(const unsigned*)&BsT[bn][akf];
            unsigned B1 = *(const unsigned*)&BsT[bn][akf + 8];
            mma16816(C[j][0], C[j][1], C[j][2], C[j][3], A0, A1, A2, A3, B0, B1);
        }
    }
    __syncthreads();
    {
        int ac = 2 * (lane & 3);
#pragma unroll
        for (int j = 0; j < 8; j++) {
            *(__half2*)&hS[arf][j * 8 + ac]     = __floats2half2_rn(C[j][0], C[j][1]);
            *(__half2*)&hS[arf + 8][j * 8 + ac] = __floats2half2_rn(C[j][2], C[j][3]);
        }
    }
    __syncthreads();

    if (t == 0) {
        for (int i = tid; i < 64 * 32; i += 128) {
            int rr = i >> 5, cc2 = i & 31;
            if (m0 + rr < NN)
                ((__half2*)&d_hh[(m0 + rr) * 64])[cc2] = *(__half2*)&hS[rr][cc2 * 2];
        }
        if (tid < 64 && m0 + tid < NN) {
            float acc = 0.f;
#pragma unroll
            for (int k2 = 0; k2 < 64; k2++)
                acc = fmaf(__half2float(hS[tid][k2]), wread[k2], acc);
            out[NN + m0 + tid] = acc;
        }
        {
            const uint4* src = (const uint4*)d_WupT;
            uint4* dst = (uint4*)WuS;
#pragma unroll
            for (int i = 0; i < 4; i++) dst[tid + i * 128] = src[tid + i * 128];
        }
        __syncthreads();
        float H[8][4];
#pragma unroll
        for (int j = 0; j < 8; j++)
#pragma unroll
            for (int i = 0; i < 4; i++) H[j][i] = 0.f;
#pragma unroll
        for (int s = 0; s < 4; s++) {
            int k0 = s * 16;
            unsigned A0 = *(const unsigned*)&hS[arf][k0 + akf];
            unsigned A1 = *(const unsigned*)&hS[arf + 8][k0 + akf];
            unsigned A2 = *(const unsigned*)&hS[arf][k0 + akf + 8];
            unsigned A3 = *(const unsigned*)&hS[arf + 8][k0 + akf + 8];
#pragma unroll
            for (int j = 0; j < 8; j++) {
                int bn = j * 8 + (lane >> 2);
                unsigned B0 = *(const unsigned*)&WuS[bn * 64 + k0 + akf];
                unsigned B1 = *(const unsigned*)&WuS[bn * 64 + k0 + akf + 8];
                mma16816(H[j][0], H[j][1], H[j][2], H[j][3], A0, A1, A2, A3, B0, B1);
            }
        }
        int ac = 2 * (lane & 3);
#pragma unroll
        for (int j = 0; j < 8; j++) {
            int col = j * 8 + ac;
            if (m0 + arf < NN) {
                d_hup[(m0 + arf) * 64 + col] = H[j][0];
                d_hup[(m0 + arf) * 64 + col + 1] = H[j][1];
            }
            if (m0 + arf + 8 < NN) {
                d_hup[(m0 + arf + 8) * 64 + col] = H[j][2];
                d_hup[(m0 + arf + 8) * 64 + col + 1] = H[j][3];
            }
        }
    } else {
        int nd = tid >> 1, hf2 = tid & 1;
        float y[8];
#pragma unroll
        for (int o = 0; o < 8; o++) y[o] = 0.f;
        for (int k2 = 0; k2 < 64; k2++) {
            float hv = __half2float(hS[nd][k2]);
#pragma unroll
            for (int o = 0; o < 8; o++)
                y[o] = fmaf(hv, Wmlp1[k2 * 16 + hf2 * 8 + o], y[o]);
        }
        float acc = 0.f;
#pragma unroll
        for (int o = 0; o < 8; o++) {
            float s2 = __fdividef(y[o], 1.0f + __expf(-y[o]));
            acc = fmaf(s2, wmlp2[hf2 * 8 + o], acc);
        }
        acc += __shfl_xor_sync(0xffffffffu, acc, 1);
        if (hf2 == 0 && m0 + nd < NN) out[2 * NN + m0 + nd] = acc;
    }
}

// ---------------- host launch ----------------
extern "C" void kernel_launch(void* const* d_in, const int* in_sizes, int n_in,
                              void* d_out, int out_size) {
    const float *positions = nullptr, *node_attrs = nullptr, *shifts = nullptr;
    const float *atomic_energies = nullptr, *W_embed = nullptr, *W_up = nullptr;
    const float *W_r1 = nullptr, *W_r2 = nullptr, *W_mix = nullptr, *W_self = nullptr;
    const float *w_read = nullptr, *W_mlp1 = nullptr, *w_mlp2 = nullptr;
    const int* edge_index = nullptr;
    for (int i = 0; i < n_in; i++) {
        switch (in_sizes[i]) {
            case 30000:  positions = (const float*)d_in[i]; break;
            case 100000: node_attrs = (const float*)d_in[i]; break;
            case 480000: shifts = (const float*)d_in[i]; break;
            case 320000: edge_index = (const int*)d_in[i]; break;
            case 10:     atomic_energies = (const float*)d_in[i]; break;
            case 640:    W_embed = (const float*)d_in[i]; break;
            case 8192:   if (!W_up) W_up = (const float*)d_in[i];
                         else W_self = (const float*)d_in[i]; break;
            case 256:    W_r1 = (const float*)d_in[i]; break;
            case 18432:  W_r2 = (const float*)d_in[i]; break;
            case 73728:  W_mix = (const float*)d_in[i]; break;
            case 64:     w_read = (const float*)d_in[i]; break;
            case 1024:   W_mlp1 = (const float*)d_in[i]; break;
            case 16:     w_mlp2 = (const float*)d_in[i]; break;
            default: break;
        }
    }
    float* out = (float*)d_out;
    (void)out_size;

    k_setup<<<SETUP_BLKS, 128>>>(positions, shifts, edge_index, node_attrs, W_embed,
                                 atomic_energies, W_up, W_mix, W_self, W_r2, out);
    k_scan<<<1, 1024>>>();
    k_scatgeo<<<GEOM_BLKS, 256>>>(edge_index, W_r1);

    for (int t = 0; t < 2; t++) {
        k_agg<<<(NN + NPB - 1) / NPB, 128>>>(t);
        k_update<<<(NN + 63) / 64, 128>>>(t, w_read, W_mlp1, w_mlp2, out);
    }
}

// round 9
// speedup vs baseline: 3.9427x; 1.0271x over previous
#include <cuda_runtime.h>
#include <cuda_fp16.h>
#include <math.h>

#define NN 10000
#define EE 160000
#define CC 64
#define RMAXF 5.0f
#define NPB 16
#define TPW_PAD 584

#define GEOM_BLKS 625
#define EMB_BLKS  5000
#define PREP_BLKS 672
#define SETUP_BLKS (GEOM_BLKS + EMB_BLKS + PREP_BLKS)

// ---------------- device scratch ----------------
__device__ float4 d_vec[EE];
__device__ float d_sh12[EE * 12];
__device__ __half d_zh[2][EE * 16];
__device__ unsigned char d_act[EE];
__device__ int   d_count[NN];
__device__ int   d_offs[NN + 1];
__device__ int   d_cursor[NN];
__device__ int   d_ssnd[EE];
__device__ float d_hup[NN * CC];
__device__ __half d_hh[NN * CC];
__device__ __half d_aggh[NN * 576];
__device__ __half d_W2T[2][576 * 16];
__device__ __half d_BT[2][64 * 640];
__device__ __half d_WupT[64 * 64];

__device__ __forceinline__ void mma16816(float& c0, float& c1, float& c2, float& c3,
                                         unsigned a0, unsigned a1, unsigned a2, unsigned a3,
                                         unsigned b0, unsigned b1) {
    asm volatile(
        "mma.sync.aligned.m16n8k16.row.col.f32.f16.f16.f32 "
        "{%0,%1,%2,%3},{%4,%5,%6,%7},{%8,%9},{%0,%1,%2,%3};\n"
        : "+f"(c0), "+f"(c1), "+f"(c2), "+f"(c3)
        : "r"(a0), "r"(a1), "r"(a2), "r"(a3), "r"(b0), "r"(b1));
}

// ---------------- fused setup ----------------
__device__ __forceinline__ void geom1_edge(int e, const float* __restrict__ pos,
                                           const float* __restrict__ shifts,
                                           const int* __restrict__ ei) {
    int s  = ei[e];
    int rv = ei[EE + e];
    float vx = pos[rv * 3 + 0] - pos[s * 3 + 0] + shifts[e * 3 + 0];
    float vy = pos[rv * 3 + 1] - pos[s * 3 + 1] + shifts[e * 3 + 1];
    float vz = pos[rv * 3 + 2] - pos[s * 3 + 2] + shifts[e * 3 + 2];
    float r = sqrtf(vx * vx + vy * vy + vz * vz) + 1e-9f;
    bool act = (r < RMAXF);
    d_act[e] = act ? 1 : 0;
    if (!act) return;
    atomicAdd(&d_count[rv], 1);
    d_vec[e] = make_float4(vx, vy, vz, r);
}

__global__ __launch_bounds__(128) void k_setup(const float* __restrict__ pos,
        const float* __restrict__ shifts, const int* __restrict__ ei,
        const float* __restrict__ na, const float* __restrict__ We,
        const float* __restrict__ ae, const float* __restrict__ Wup,
        const float* __restrict__ Wmix, const float* __restrict__ Wself,
        const float* __restrict__ Wr2, float* __restrict__ out) {
    int b = blockIdx.x, tid = threadIdx.x;
    if (b < GEOM_BLKS) {
        int e0 = b * 256 + tid;
        geom1_edge(e0, pos, shifts, ei);
        geom1_edge(e0 + 128, pos, shifts, ei);
    } else if (b < GEOM_BLKS + EMB_BLKS) {
        __shared__ float hs[128];
        int slot = tid >> 6, c = tid & 63;
        int n = (b - GEOM_BLKS) * 2 + slot;
        float acc = 0.f;
#pragma unroll
        for (int k = 0; k < 10; k++) acc = fmaf(na[n * 10 + k], We[k * 64 + c], acc);
        hs[tid] = acc;
        d_hh[n * 64 + c] = __float2half(acc);
        if (c == 0) {
            float r = 0.f;
#pragma unroll
            for (int k = 0; k < 10; k++) r = fmaf(na[n * 10 + k], ae[k], r);
            out[n] = r;
        }
        __syncthreads();
        float hu = 0.f;
#pragma unroll
        for (int k = 0; k < 64; k++) hu = fmaf(hs[slot * 64 + k], Wup[k * 64 + c], hu);
        d_hup[n * 64 + c] = hu;
    } else {
        int i = (b - GEOM_BLKS - EMB_BLKS) * 128 + tid;
        if (i < 81920) {
            int t = i / 40960, r = i - t * 40960, n = r / 640, k = r - n * 640;
            float v = (k < 576) ? Wmix[t * 36864 + k * 64 + n]
                                : Wself[t * 4096 + (k - 576) * 64 + n];
            d_BT[t][r] = __float2half(v);
        } else if (i < 86016) {
            int q = i - 81920;
            int o = q >> 6, ii = q & 63;
            d_WupT[q] = __float2half(Wup[4096 + ii * 64 + o]);
        }
        int j = i;
        if (j < 2 * 9216) {
            int t = j / 9216, r = j - t * 9216, cg = r >> 4, m = r & 15;
            d_W2T[t][r] = __float2half(Wr2[t * 9216 + m * 576 + cg]);
        }
    }
}

// ---------------- single-kernel scan ----------------
__global__ __launch_bounds__(1024) void k_scan() {
    __shared__ int ws[32];
    __shared__ int tot_s;
    int t = threadIdx.x, lane = t & 31, w = t >> 5;
    int run = 0;
    for (int rr = 0; rr < 10; rr++) {
        int idx = rr * 1024 + t;
        int v = 0;
        if (idx < NN) { v = d_count[idx]; d_count[idx] = 0; }
        int inc = v;
#pragma unroll
        for (int o = 1; o < 32; o <<= 1) {
            int u = __shfl_up_sync(0xffffffffu, inc, o);
            if (lane >= o) inc += u;
        }
        if (lane == 31) ws[w] = inc;
        __syncthreads();
        if (w == 0) {
            int x = ws[lane];
            int xi = x;
#pragma unroll
            for (int o = 1; o < 32; o <<= 1) {
                int u = __shfl_up_sync(0xffffffffu, xi, o);
                if (lane >= o) xi += u;
            }
            ws[lane] = xi - x;
            if (lane == 31) tot_s = xi;
        }
        __syncthreads();
        int excl = run + ws[w] + inc - v;
        if (idx < NN) { d_offs[idx] = excl; d_cursor[idx] = excl; }
        run += tot_s;
        __syncthreads();
    }
    if (t == 0) d_offs[NN] = run;
}

// ---------------- fused scatter + heavy geometry ----------------
__global__ __launch_bounds__(256) void k_scatgeo(const int* __restrict__ ei,
                                                 const float* __restrict__ Wr1) {
    __shared__ float Ws[256];
    Ws[threadIdx.x] = Wr1[threadIdx.x];
    __syncthreads();
    int e = blockIdx.x * 256 + threadIdx.x;
    if (e >= EE || !d_act[e]) return;
    int rv = ei[EE + e];
    int p = atomicAdd(&d_cursor[rv], 1);
    d_ssnd[p] = ei[e];

    float4 v = d_vec[e];
    float r = v.w;
    float inv = __fdividef(1.0f, r);
    float ux = v.x * inv, uy = v.y * inv, uz = v.z * inv;
    const float s3 = 1.7320508075688772f, s5 = 2.2360679774997896f, s15 = 3.872983346207417f;
    float4 fA = make_float4(1.0f, s3 * ux, s3 * uy, s3 * uz);
    float4 fB = make_float4(s15 * ux * uy, s15 * uy * uz,
                            0.5f * s5 * (3.0f * uz * uz - 1.0f), s15 * ux * uz);
    float4 fC = make_float4(0.5f * s15 * (ux * ux - uy * uy), 0.f, 0.f, 0.f);
    float4* shp = (float4*)&d_sh12[(long)p * 12];
    shp[0] = fA; shp[1] = fB; shp[2] = fC;

    float xx = r * (1.0f / RMAXF);
    float th = 3.14159265358979323846f * xx;
    float s1, c1;
    __sincosf(th, &s1, &c1);
    float x2 = xx * xx;
    float x6 = x2 * x2 * x2;
    float fc = 1.0f + x6 * (-28.0f + xx * (48.0f - 21.0f * xx));
    float pref = 0.6324555320336759f * inv * fc;
    float ef[8];
    float sp = 0.0f, sc = s1, c2 = 2.0f * c1;
#pragma unroll
    for (int n = 0; n < 8; n++) {
        ef[n] = pref * sc;
        float nx = c2 * sc - sp;
        sp = sc; sc = nx;
    }
#pragma unroll
    for (int t = 0; t < 2; t++) {
        float a[16];
#pragma unroll
        for (int m = 0; m < 16; m++) {
            float acc = 0.f;
#pragma unroll
            for (int n = 0; n < 8; n++) acc = fmaf(ef[n], Ws[t * 128 + n * 16 + m], acc);
            a[m] = __fdividef(acc, 1.0f + __expf(-acc));
        }
        __half2 hz[8];
#pragma unroll
        for (int q = 0; q < 8; q++) hz[q] = __floats2half2_rn(a[2 * q], a[2 * q + 1]);
        uint4* zp = (uint4*)&d_zh[t][(long)p * 16];
        zp[0] = *(uint4*)&hz[0];
        zp[1] = *(uint4*)&hz[4];
    }
}

// ---------------- agg: pipelined MMA tp_w + scalar epilogue ----------------
template<int SOFF, int SCNT>
__device__ __forceinline__ void agg_core(int tid, int c, int n0,
        const __half* __restrict__ zg,
        const unsigned* Bf0, const unsigned* Bf1,
        float (*tpwS)[TPW_PAD], float (*hupS)[64],
        __half (*zS)[16][16], float (*shS)[16][12], int (*sndS)[16],
        const int* offsS) {
    int lane = tid & 31, w = tid >> 5;
    int ar = lane >> 2, ak = (lane & 3) * 2;
    int iBeg = offsS[0], iEnd = offsS[NPB];
    int nChunks = (iEnd - iBeg + 15) >> 4;
    int kn = 0, nextb = offsS[1];
    float acc[SCNT];
#pragma unroll
    for (int j = 0; j < SCNT; j++) acc[j] = 0.f;

    // staging roles (disjoint):
    //  tid<32: z (edge tid>>1, half tid&1) ; tid in [32,80): sh ; [80,96): snd
    int zE = tid >> 1, zP = tid & 1;
    int shI = tid - 32, shE = shI / 3, shP = shI - shE * 3;
    int snE = tid - 80;
    int hE = tid >> 3, hQ = tid & 7;   // hup gather role (all threads)

    // prologue: stage chunk 0 directly
    if (nChunks > 0) {
        long basec = iBeg;
        if (tid < 32) {
            long idx = basec + zE; if (idx > iEnd - 1) idx = iEnd - 1;
            *(uint4*)&zS[0][zE][zP * 8] = *(const uint4*)&zg[idx * 16 + zP * 8];
        } else if (tid < 80) {
            long idx = basec + shE; if (idx > iEnd - 1) idx = iEnd - 1;
            *(float4*)&shS[0][shE][shP * 4] = *(const float4*)&d_sh12[idx * 12 + shP * 4];
        } else if (tid < 96) {
            long idx = basec + snE; if (idx > iEnd - 1) idx = iEnd - 1;
            sndS[0][snE] = d_ssnd[idx];
        }
    }
    __syncthreads();

    int cur = 0;
    for (int k = 0; k < nChunks; k++) {
        int base = iBeg + k * 16;
        int cnt = min(16, iEnd - base);
        int nxt = cur ^ 1;
        // (A) prefetch chunk k+1 into regs
        uint4 zreg; float4 shreg; int snreg = 0;
        bool hasNext = (k + 1 < nChunks);
        if (hasNext) {
            long b2 = base + 16;
            if (tid < 32) {
                long idx = b2 + zE; if (idx > iEnd - 1) idx = iEnd - 1;
                zreg = *(const uint4*)&zg[idx * 16 + zP * 8];
            } else if (tid < 80) {
                long idx = b2 + shE; if (idx > iEnd - 1) idx = iEnd - 1;
                shreg = *(const float4*)&d_sh12[idx * 12 + shP * 4];
            } else if (tid < 96) {
                long idx = b2 + snE; if (idx > iEnd - 1) idx = iEnd - 1;
                snreg = d_ssnd[idx];
            }
        }
        // (B) hup gather for current chunk (snd staged previous iter)
        int sn = (hE < cnt) ? sndS[cur][hE] : 0;
        const float4* hp = (const float4*)&d_hup[sn * 64 + hQ * 8];
        float4 h0 = hp[0], h1 = hp[1];
        // (C) MMA from zS[cur] -> tpwS
        unsigned A0 = *(const unsigned*)&zS[cur][ar][ak];
        unsigned A1 = *(const unsigned*)&zS[cur][ar + 8][ak];
        unsigned A2 = *(const unsigned*)&zS[cur][ar][ak + 8];
        unsigned A3 = *(const unsigned*)&zS[cur][ar + 8][ak + 8];
#pragma unroll
        for (int q = 0; q < 18; q++) {
            int cb = (w * 18 + q) * 8;
            float c0 = 0.f, c1 = 0.f, c2 = 0.f, c3 = 0.f;
            mma16816(c0, c1, c2, c3, A0, A1, A2, A3, Bf0[q], Bf1[q]);
            int cg0 = cb + 2 * (lane & 3);
            *(float2*)&tpwS[ar][cg0]     = make_float2(c0, c1);
            *(float2*)&tpwS[ar + 8][cg0] = make_float2(c2, c3);
        }
        // (D) store hup + prefetch buffers
        *(float4*)&hupS[hE][hQ * 8] = h0;
        *(float4*)&hupS[hE][hQ * 8 + 4] = h1;
        if (hasNext) {
            if (tid < 32)      *(uint4*)&zS[nxt][zE][zP * 8] = zreg;
            else if (tid < 80) *(float4*)&shS[nxt][shE][shP * 4] = shreg;
            else if (tid < 96) sndS[nxt][snE] = snreg;
        }
        __syncthreads();
        // (E) epilogue
        for (int e = 0; e < cnt; e++) {
            int i = base + e;
            while (i >= nextb) {
#pragma unroll
                for (int j = 0; j < SCNT; j++)
                    d_aggh[(long)(n0 + kn) * 576 + c * 9 + SOFF + j] =
                        __float2half(acc[j] * (1.0f / 32.0f));
#pragma unroll
                for (int j = 0; j < SCNT; j++) acc[j] = 0.f;
                kn++;
                nextb = (kn < NPB) ? offsS[kn + 1] : 0x7fffffff;
            }
            float hv = hupS[e][c];
#pragma unroll
            for (int j = 0; j < SCNT; j++)
                acc[j] = fmaf(hv * shS[cur][e][SOFF + j], tpwS[e][c * 9 + SOFF + j], acc[j]);
        }
        __syncthreads();   // protect tpwS/hupS before next chunk's stores
        cur = nxt;
    }
    while (kn < NPB) {
#pragma unroll
        for (int j = 0; j < SCNT; j++)
            d_aggh[(long)(n0 + kn) * 576 + c * 9 + SOFF + j] =
                __float2half(acc[j] * (1.0f / 32.0f));
#pragma unroll
        for (int j = 0; j < SCNT; j++) acc[j] = 0.f;
        kn++;
    }
}

__global__ __launch_bounds__(128) void k_agg(int t) {
    __shared__ float tpwS[16][TPW_PAD];
    __shared__ float hupS[16][64];
    __shared__ __half zS[2][16][16];
    __shared__ float shS[2][16][12];
    __shared__ int sndS[2][16];
    __shared__ int offsS[NPB + 1];
    int tid = threadIdx.x, lane = tid & 31, w = tid >> 5;
    int n0 = blockIdx.x * NPB;
    if (tid < NPB + 1) offsS[tid] = d_offs[n0 + tid];

    const __half* W2 = d_W2T[t];
    unsigned Bf0[18], Bf1[18];
    int ar = lane >> 2, ak = (lane & 3) * 2;
#pragma unroll
    for (int q = 0; q < 18; q++) {
        int cb = (w * 18 + q) * 8;
        Bf0[q] = *(const unsigned*)&W2[(cb + ar) * 16 + ak];
        Bf1[q] = *(const unsigned*)&W2[(cb + ar) * 16 + ak + 8];
    }
    __syncthreads();
    const __half* zg = d_zh[t];
    int c = tid & 63;
    if (tid < 64) agg_core<0, 5>(tid, c, n0, zg, Bf0, Bf1, tpwS, hupS, zS, shS, sndS, offsS);
    else          agg_core<5, 4>(tid, c, n0, zg, Bf0, Bf1, tpwS, hupS, zS, shS, sndS, offsS);
}

// ---------------- update: fp16 MMA GEMM + fused epilogues ----------------
__global__ __launch_bounds__(128) void k_update(int t, const float* __restrict__ wread,
                                                const float* __restrict__ Wmlp1,
                                                const float* __restrict__ wmlp2,
                                                float* __restrict__ out) {
    __shared__ __half As[64][16];
    __shared__ __half BsT[64][16];
    __shared__ __half hS[64][72];
    __shared__ __half WuS[64 * 64];
    int tid = threadIdx.x, lane = tid & 31, w = tid >> 5;
    int m0 = blockIdx.x * 64;
    float C[8][4];
#pragma unroll
    for (int j = 0; j < 8; j++)
#pragma unroll
        for (int i = 0; i < 4; i++) C[j][i] = 0.f;

    int r = tid >> 1, hf = tid & 1;
    int node = m0 + r;
    int arf = 16 * w + (lane >> 2), akf = (lane & 3) * 2;

    for (int step = 0; step < 40; step++) {
        int k0 = step * 16;
        uint4 av = make_uint4(0, 0, 0, 0);
        if (node < NN) {
            const uint4* ap = (k0 < 576) ? (const uint4*)&d_aggh[(long)node * 576 + k0]
                                         : (const uint4*)&d_hh[node * 64 + (k0 - 576)];
            av = ap[hf];
        }
        uint4 bv = *((const uint4*)&d_BT[t][r * 640 + k0] + hf);
        __syncthreads();
        *(uint4*)&As[r][hf * 8] = av;
        *(uint4*)&BsT[r][hf * 8] = bv;
        __syncthreads();
        unsigned A0 = *(const unsigned*)&As[arf][akf];
        unsigned A1 = *(const unsigned*)&As[arf + 8][akf];
        unsigned A2 = *(const unsigned*)&As[arf][akf + 8];
        unsigned A3 = *(const unsigned*)&As[arf + 8][akf + 8];
#pragma unroll
        for (int j = 0; j < 8; j++) {
            int bn = j * 8 + (lane >> 2);
            unsigned B0 = *(const unsigned*)&BsT[bn][akf];
            unsigned B1 = *(const unsigned*)&BsT[bn][akf + 8];
            mma16816(C[j][0], C[j][1], C[j][2], C[j][3], A0, A1, A2, A3, B0, B1);
        }
    }
    __syncthreads();
    {
        int ac = 2 * (lane & 3);
#pragma unroll
        for (int j = 0; j < 8; j++) {
            *(__half2*)&hS[arf][j * 8 + ac]     = __floats2half2_rn(C[j][0], C[j][1]);
            *(__half2*)&hS[arf + 8][j * 8 + ac] = __floats2half2_rn(C[j][2], C[j][3]);
        }
    }
    __syncthreads();

    if (t == 0) {
        for (int i = tid; i < 64 * 32; i += 128) {
            int rr = i >> 5, cc2 = i & 31;
            if (m0 + rr < NN)
                ((__half2*)&d_hh[(m0 + rr) * 64])[cc2] = *(__half2*)&hS[rr][cc2 * 2];
        }
        if (tid < 64 && m0 + tid < NN) {
            float acc = 0.f;
#pragma unroll
            for (int k2 = 0; k2 < 64; k2++)
                acc = fmaf(__half2float(hS[tid][k2]), wread[k2], acc);
            out[NN + m0 + tid] = acc;
        }
        {
            const uint4* src = (const uint4*)d_WupT;
            uint4* dst = (uint4*)WuS;
#pragma unroll
            for (int i = 0; i < 4; i++) dst[tid + i * 128] = src[tid + i * 128];
        }
        __syncthreads();
        float H[8][4];
#pragma unroll
        for (int j = 0; j < 8; j++)
#pragma unroll
            for (int i = 0; i < 4; i++) H[j][i] = 0.f;
#pragma unroll
        for (int s = 0; s < 4; s++) {
            int k0 = s * 16;
            unsigned A0 = *(const unsigned*)&hS[arf][k0 + akf];
            unsigned A1 = *(const unsigned*)&hS[arf + 8][k0 + akf];
            unsigned A2 = *(const unsigned*)&hS[arf][k0 + akf + 8];
            unsigned A3 = *(const unsigned*)&hS[arf + 8][k0 + akf + 8];
#pragma unroll
            for (int j = 0; j < 8; j++) {
                int bn = j * 8 + (lane >> 2);
                unsigned B0 = *(const unsigned*)&WuS[bn * 64 + k0 + akf];
                unsigned B1 = *(const unsigned*)&WuS[bn * 64 + k0 + akf + 8];
                mma16816(H[j][0], H[j][1], H[j][2], H[j][3], A0, A1, A2, A3, B0, B1);
            }
        }
        int ac = 2 * (lane & 3);
#pragma unroll
        for (int j = 0; j < 8; j++) {
            int col = j * 8 + ac;
            if (m0 + arf < NN) {
                d_hup[(m0 + arf) * 64 + col] = H[j][0];
                d_hup[(m0 + arf) * 64 + col + 1] = H[j][1];
            }
            if (m0 + arf + 8 < NN) {
                d_hup[(m0 + arf + 8) * 64 + col] = H[j][2];
                d_hup[(m0 + arf + 8) * 64 + col + 1] = H[j][3];
            }
        }
    } else {
        int nd = tid >> 1, hf2 = tid & 1;
        float y[8];
#pragma unroll
        for (int o = 0; o < 8; o++) y[o] = 0.f;
        for (int k2 = 0; k2 < 64; k2++) {
            float hv = __half2float(hS[nd][k2]);
#pragma unroll
            for (int o = 0; o < 8; o++)
                y[o] = fmaf(hv, Wmlp1[k2 * 16 + hf2 * 8 + o], y[o]);
        }
        float acc = 0.f;
#pragma unroll
        for (int o = 0; o < 8; o++) {
            float s2 = __fdividef(y[o], 1.0f + __expf(-y[o]));
            acc = fmaf(s2, wmlp2[hf2 * 8 + o], acc);
        }
        acc += __shfl_xor_sync(0xffffffffu, acc, 1);
        if (hf2 == 0 && m0 + nd < NN) out[2 * NN + m0 + nd] = acc;
    }
}

// ---------------- host launch ----------------
extern "C" void kernel_launch(void* const* d_in, const int* in_sizes, int n_in,
                              void* d_out, int out_size) {
    const float *positions = nullptr, *node_attrs = nullptr, *shifts = nullptr;
    const float *atomic_energies = nullptr, *W_embed = nullptr, *W_up = nullptr;
    const float *W_r1 = nullptr, *W_r2 = nullptr, *W_mix = nullptr, *W_self = nullptr;
    const float *w_read = nullptr, *W_mlp1 = nullptr, *w_mlp2 = nullptr;
    const int* edge_index = nullptr;
    for (int i = 0; i < n_in; i++) {
        switch (in_sizes[i]) {
            case 30000:  positions = (const float*)d_in[i]; break;
            case 100000: node_attrs = (const float*)d_in[i]; break;
            case 480000: shifts = (const float*)d_in[i]; break;
            case 320000: edge_index = (const int*)d_in[i]; break;
            case 10:     atomic_energies = (const float*)d_in[i]; break;
            case 640:    W_embed = (const float*)d_in[i]; break;
            case 8192:   if (!W_up) W_up = (const float*)d_in[i];
                         else W_self = (const float*)d_in[i]; break;
            case 256:    W_r1 = (const float*)d_in[i]; break;
            case 18432:  W_r2 = (const float*)d_in[i]; break;
            case 73728:  W_mix = (const float*)d_in[i]; break;
            case 64:     w_read = (const float*)d_in[i]; break;
            case 1024:   W_mlp1 = (const float*)d_in[i]; break;
            case 16:     w_mlp2 = (const float*)d_in[i]; break;
            default: break;
        }
    }
    float* out = (float*)d_out;
    (void)out_size;

    k_setup<<<SETUP_BLKS, 128>>>(positions, shifts, edge_index, node_attrs, W_embed,
                                 atomic_energies, W_up, W_mix, W_self, W_r2, out);
    k_scan<<<1, 1024>>>();
    k_scatgeo<<<GEOM_BLKS, 256>>>(edge_index, W_r1);

    for (int t = 0; t < 2; t++) {
        k_agg<<<(NN + NPB - 1) / NPB, 128>>>(t);
        k_update<<<(NN + 63) / 64, 128>>>(t, w_read, W_mlp1, w_mlp2, out);
    }
}